// round 13
// baseline (speedup 1.0000x reference)
#include <cuda_runtime.h>
#include <math.h>
#include <stdint.h>

// Problem constants
#define BATCH    2
#define T_SEQ    2048
#define D_MODEL  1024
#define N_HEADS  16
#define HEAD_DIM 64
#define M_TOTAL  (BATCH * T_SEQ)          // 4096 rows
#define QKV_LD   (3 * D_MODEL)            // 3072

// Scratch (allocation-free rule: __device__ globals)
__device__ float g_qkv   [M_TOTAL * QKV_LD];    // [4096, 3072] tf32-rounded (gemm<ROUND>)
__device__ float g_attn  [M_TOTAL * D_MODEL];   // [4096, 1024] tf32-rounded by flash
__device__ float g_xr    [M_TOTAL * D_MODEL];   // tf32-rounded x
__device__ float g_wqkv_r[D_MODEL * QKV_LD];    // tf32-rounded w_qkv
__device__ float g_wout_r[D_MODEL * D_MODEL];   // tf32-rounded w_out

__device__ __forceinline__ float to_tf32(float x) {
    float y;
    asm("cvt.rna.tf32.f32 %0, %1;" : "=f"(y) : "f"(x));
    return y;
}
__device__ __forceinline__ uint32_t smem_u32(const void* p) {
    uint32_t a;
    asm("{ .reg .u64 t; cvta.to.shared.u64 t, %1; cvt.u32.u64 %0, t; }" : "=r"(a) : "l"(p));
    return a;
}
__device__ __forceinline__ void cp16(uint32_t dst, const void* src) {
    asm volatile("cp.async.cg.shared.global [%0], [%1], 16;" :: "r"(dst), "l"(src) : "memory");
}
#define MMA_TF32(D, A, B) \
    asm volatile("mma.sync.aligned.m16n8k8.row.col.f32.tf32.tf32.f32 " \
                 "{%0,%1,%2,%3}, {%4,%5,%6,%7}, {%8,%9}, {%0,%1,%2,%3};" \
                 : "+f"((D)[0]), "+f"((D)[1]), "+f"((D)[2]), "+f"((D)[3]) \
                 : "r"((A)[0]), "r"((A)[1]), "r"((A)[2]), "r"((A)[3]), \
                   "r"((B)[0]), "r"((B)[1]))
#define LDMATRIX_X4(R, ADDR) \
    asm volatile("ldmatrix.sync.aligned.m8n8.x4.shared.b16 {%0,%1,%2,%3}, [%4];" \
                 : "=r"((R)[0]), "=r"((R)[1]), "=r"((R)[2]), "=r"((R)[3]) : "r"(ADDR))

// ---------------------------------------------------------------------------
// tf32 mma.sync GEMM — R13: 256x128 block tile, 8 warps as 4x2, warp tile
// 64x64 (4 m-atoms x 8 n-atoms). Fragment bytes/MAC: 0.25 -> 0.168 (the
// kernel is smem-crossbar-bound; squarer warp tiles are the only lever).
// 1 CTA/SM (regs ~185), 3-stage cp.async, K-tile 32.
// smem: A [256][36] (ldmatrix stride 9x16B, conflict-free),
//       B [32][136]  (stride 8 mod 32 -> banks 8*tig+g all distinct).
// ---------------------------------------------------------------------------
#define GB_A_FLOATS (256 * 36)                    // 9216
#define GB_B_FLOATS (32 * 136)                    // 4352
#define GB_STAGE    (GB_A_FLOATS + GB_B_FLOATS)   // 13568 floats
#define GB_SMEM_BYTES (3 * GB_STAGE * 4)          // 162816 B

__device__ __forceinline__ void issue_stage_big(uint32_t sb, const float* __restrict__ A,
                                                const float* __restrict__ B,
                                                int tid, int row0, int col0, int k0,
                                                int N, int K) {
#pragma unroll
    for (int i = 0; i < 8; i++) {                 // A: 256x32 = 2048 float4
        int ff = tid + i * 256;
        int r  = ff >> 3, c4 = (ff & 7) * 4;
        cp16(sb + (r * 36 + c4) * 4, &A[(size_t)(row0 + r) * K + k0 + c4]);
    }
#pragma unroll
    for (int i = 0; i < 4; i++) {                 // B: 32x128 = 1024 float4
        int ff = tid + i * 256;
        int k  = ff >> 5, n4 = (ff & 31) * 4;
        cp16(sb + (GB_A_FLOATS + k * 136 + n4) * 4, &B[(size_t)(k0 + k) * N + col0 + n4]);
    }
}

template <bool ROUND>
__global__ __launch_bounds__(256, 1) void gemm_mma_big(const float* __restrict__ A,
                                                       const float* __restrict__ B,
                                                       float* __restrict__ C,
                                                       int M, int N, int K) {
    extern __shared__ __align__(16) float gsm[];
    const uint32_t sb = smem_u32(gsm);
    const int tid  = threadIdx.x;
    const int lane = tid & 31;
    const int wid  = tid >> 5;
    const int wr = wid >> 1, wc = wid & 1;        // 4x2 warp grid
    const int g  = lane >> 2, tig = lane & 3;
    const int row0 = blockIdx.y * 256;
    const int col0 = blockIdx.x * 128;

    float d[4][8][4] = {};
    const int T = K >> 5;

    issue_stage_big(sb + 0 * GB_STAGE * 4, A, B, tid, row0, col0, 0, N, K);
    asm volatile("cp.async.commit_group;" ::: "memory");
    issue_stage_big(sb + 1 * GB_STAGE * 4, A, B, tid, row0, col0, 32, N, K);
    asm volatile("cp.async.commit_group;" ::: "memory");

    const uint32_t a_base = sb + ((wr * 64 + ((lane >> 3) & 1) * 8 + (lane & 7)) * 36
                                  + ((lane >> 4) & 1) * 4) * 4;
    const int bcol = wc * 64 + g;

    for (int t = 0; t < T; t++) {
        const int s = t % 3;
        asm volatile("cp.async.wait_group 1;" ::: "memory");
        __syncthreads();

        const uint32_t aS = a_base + s * GB_STAGE * 4;
        const uint32_t* sBu = (const uint32_t*)(gsm + s * GB_STAGE + GB_A_FLOATS);

#pragma unroll
        for (int ks = 0; ks < 4; ks++) {
            uint32_t af[4][4], bf[8][2];
#pragma unroll
            for (int ma = 0; ma < 4; ma++)
                LDMATRIX_X4(af[ma], aS + ma * 2304 + ks * 32);
#pragma unroll
            for (int na = 0; na < 8; na++) {
                bf[na][0] = sBu[(ks * 8 + tig) * 136 + bcol + na * 8];
                bf[na][1] = sBu[(ks * 8 + tig + 4) * 136 + bcol + na * 8];
            }
#pragma unroll
            for (int ma = 0; ma < 4; ma++)
#pragma unroll
                for (int na = 0; na < 8; na++)
                    MMA_TF32(d[ma][na], af[ma], bf[na]);
        }

        if (t + 2 < T)
            issue_stage_big(sb + ((t + 2) % 3) * GB_STAGE * 4, A, B, tid,
                            row0, col0, (t + 2) * 32, N, K);
        asm volatile("cp.async.commit_group;" ::: "memory");
    }

#pragma unroll
    for (int ma = 0; ma < 4; ma++)
#pragma unroll
        for (int na = 0; na < 8; na++) {
            const int r = row0 + wr * 64 + ma * 16 + g;
            const int c = col0 + wc * 64 + na * 8 + tig * 2;
            float4 v = make_float4(d[ma][na][0], d[ma][na][1], d[ma][na][2], d[ma][na][3]);
            if (ROUND) {
                v.x = to_tf32(v.x); v.y = to_tf32(v.y);
                v.z = to_tf32(v.z); v.w = to_tf32(v.w);
            }
            *(float2*)&C[(size_t)r * N + c]       = make_float2(v.x, v.y);
            *(float2*)&C[(size_t)(r + 8) * N + c] = make_float2(v.z, v.w);
        }
}

// ---------------------------------------------------------------------------
// Fused tf32 pre-round: one kernel covers x, w_qkv, w_out
// ---------------------------------------------------------------------------
#define RN_X  (M_TOTAL * D_MODEL / 4)       // 1048576 float4
#define RN_WQ (D_MODEL * QKV_LD / 4)        //  786432
#define RN_WO (D_MODEL * D_MODEL / 4)       //  262144
#define RN_TOTAL (RN_X + RN_WQ + RN_WO)     // 2097152

__global__ void round_all_kernel(const float* __restrict__ x,
                                 const float* __restrict__ wq,
                                 const float* __restrict__ wo) {
    int i = blockIdx.x * blockDim.x + threadIdx.x;
    if (i >= RN_TOTAL) return;
    const float4* src;
    float4* dst;
    if (i < RN_X) {
        src = (const float4*)x + i;          dst = (float4*)g_xr + i;
    } else if (i < RN_X + RN_WQ) {
        src = (const float4*)wq + (i - RN_X); dst = (float4*)g_wqkv_r + (i - RN_X);
    } else {
        src = (const float4*)wo + (i - RN_X - RN_WQ);
        dst = (float4*)g_wout_r + (i - RN_X - RN_WQ);
    }
    float4 v = *src;
    v.x = to_tf32(v.x); v.y = to_tf32(v.y);
    v.z = to_tf32(v.z); v.w = to_tf32(v.w);
    *dst = v;
}

// ---------------------------------------------------------------------------
// Causal flash attention (tf32 mma.sync) — R12 config (4 CTAs/SM, single
// barrier per key-tile iteration, Q pre-scaled by 1/8).
// ---------------------------------------------------------------------------
#define FK_STRIDE 68
#define FV_STRIDE 72
#define FP_STRIDE 36                                        // 32 keys + 4 pad
#define F_STAGE_FLOATS (32 * FK_STRIDE + 32 * FV_STRIDE)    // 4480
#define F_PS (2 * F_STAGE_FLOATS)                           // 8960
#define F_SMEM_FLOATS (F_PS + 64 * FP_STRIDE)               // 11264 fl = 45056 B

__global__ __launch_bounds__(128, 4) void flash_mma_kernel() {
    extern __shared__ __align__(16) float fsm[];
    const uint32_t sb = smem_u32(fsm);
    const int tid  = threadIdx.x;
    const int lane = tid & 31;
    const int wid  = tid >> 5;        // 0..3, warp owns q rows [16wid,16wid+16)
    const int g    = lane >> 2;
    const int tig  = lane & 3;

    const int qt = (gridDim.x - 1) - blockIdx.x;     // reversed: heavy first
    const int bh = blockIdx.y;
    const int b  = bh >> 4;
    const int h  = bh & 15;
    const int q0 = qt * 64;

    const float* base = g_qkv + (size_t)b * T_SEQ * QKV_LD + h * HEAD_DIM;
    const float* Qg = base;
    const float* Kg = base + D_MODEL;
    const float* Vg = base + 2 * D_MODEL;

    // ---- prologue: Q (64x64) -> stage-0 region; KV(0) -> stage 1 ----
#pragma unroll
    for (int i = 0; i < 8; i++) {
        int ff = tid + i * 128;
        int r  = ff >> 4;
        int d4 = (ff & 15) * 4;
        cp16(sb + (r * FK_STRIDE + d4) * 4, &Qg[(size_t)(q0 + r) * QKV_LD + d4]);
    }
    asm volatile("cp.async.commit_group;" ::: "memory");
#pragma unroll
    for (int i = 0; i < 4; i++) {
        int ff = tid + i * 128;
        int r  = ff >> 4;
        int d4 = (ff & 15) * 4;
        const size_t grow = (size_t)r * QKV_LD + d4;
        cp16(sb + (F_STAGE_FLOATS + r * FK_STRIDE + d4) * 4, &Kg[grow]);
        cp16(sb + (F_STAGE_FLOATS + 32 * FK_STRIDE + r * FV_STRIDE + d4) * 4, &Vg[grow]);
    }
    asm volatile("cp.async.commit_group;" ::: "memory");
    asm volatile("cp.async.wait_group 1;" ::: "memory");   // Q complete
    __syncthreads();

    // ---- extract Q fragments once; pre-scale by 1/8 (exact on tf32) ----
    const int lm_rr  = ((lane >> 3) & 1) * 8 + (lane & 7);
    const int lm_col = ((lane >> 4) & 1) * 4;
    uint32_t qf[8][4];
    {
        const uint32_t q_lm = sb + ((wid * 16 + lm_rr) * FK_STRIDE + lm_col) * 4;
#pragma unroll
        for (int ks = 0; ks < 8; ks++) {
            LDMATRIX_X4(qf[ks], q_lm + ks * 32);
#pragma unroll
            for (int r = 0; r < 4; r++)
                qf[ks][r] = __float_as_uint(__uint_as_float(qf[ks][r]) * 0.125f);
        }
    }

    const uint32_t p_lm = sb + (F_PS + (wid * 16 + lm_rr) * FP_STRIDE + lm_col) * 4;

    const float NEG_INF = __int_as_float(0xff800000u);
    float o[8][4] = {};
    float m0 = NEG_INF, m1 = NEG_INF, l0 = 0.f, l1 = 0.f;

    const int nkt = 2 * qt + 2;                       // 32-key tiles
    for (int kt = 0; kt < nkt; kt++) {
        const int s = (kt + 1) & 1;                   // stage holding KV(kt)

        asm volatile("cp.async.wait_group 0;" ::: "memory");
        __syncthreads();          // (a) KV(kt) visible; (b) stage (kt&1) free

        if (kt + 1 < nkt) {
            const int sd = kt & 1;
#pragma unroll
            for (int i = 0; i < 4; i++) {
                int ff = tid + i * 128;
                int r  = ff >> 4;
                int d4 = (ff & 15) * 4;
                const size_t grow = (size_t)((kt + 1) * 32 + r) * QKV_LD + d4;
                cp16(sb + (sd * F_STAGE_FLOATS + r * FK_STRIDE + d4) * 4, &Kg[grow]);
                cp16(sb + (sd * F_STAGE_FLOATS + 32 * FK_STRIDE + r * FV_STRIDE + d4) * 4,
                     &Vg[grow]);
            }
            asm volatile("cp.async.commit_group;" ::: "memory");
        }

        const float* Ks = fsm + s * F_STAGE_FLOATS;
        const float* Vs = Ks + 32 * FK_STRIDE;

        // ---- S = Q K^T : 8 ks x 4 na (32 keys); Q pre-scaled ----
        float sfrag[4][4] = {};
#pragma unroll
        for (int ks = 0; ks < 8; ks++) {
#pragma unroll
            for (int na = 0; na < 4; na++) {
                uint32_t bf[2];
                bf[0] = __float_as_uint(Ks[(na * 8 + g) * FK_STRIDE + ks * 8 + tig]);
                bf[1] = __float_as_uint(Ks[(na * 8 + g) * FK_STRIDE + ks * 8 + tig + 4]);
                MMA_TF32(sfrag[na], qf[ks], bf);
            }
        }

        // ---- causal mask ----
        const bool diag = (kt >= 2 * qt);
        const int qr0 = q0 + wid * 16 + g;
        const int qr1 = qr0 + 8;
        if (diag) {
#pragma unroll
            for (int na = 0; na < 4; na++) {
                const int kg = kt * 32 + na * 8 + 2 * tig;
                if (kg     > qr0) sfrag[na][0] = NEG_INF;
                if (kg + 1 > qr0) sfrag[na][1] = NEG_INF;
                if (kg     > qr1) sfrag[na][2] = NEG_INF;
                if (kg + 1 > qr1) sfrag[na][3] = NEG_INF;
            }
        }

        // ---- online softmax (rows g / g+8; reduce across quad tig) ----
        float mx0 = NEG_INF, mx1 = NEG_INF;
#pragma unroll
        for (int na = 0; na < 4; na++) {
            mx0 = fmaxf(mx0, fmaxf(sfrag[na][0], sfrag[na][1]));
            mx1 = fmaxf(mx1, fmaxf(sfrag[na][2], sfrag[na][3]));
        }
        mx0 = fmaxf(mx0, __shfl_xor_sync(0xffffffffu, mx0, 1));
        mx0 = fmaxf(mx0, __shfl_xor_sync(0xffffffffu, mx0, 2));
        mx1 = fmaxf(mx1, __shfl_xor_sync(0xffffffffu, mx1, 1));
        mx1 = fmaxf(mx1, __shfl_xor_sync(0xffffffffu, mx1, 2));
        const float mn0 = fmaxf(m0, mx0);
        const float mn1 = fmaxf(m1, mx1);
        const float a0 = __expf(m0 - mn0);
        const float a1 = __expf(m1 - mn1);
        float sum0 = 0.f, sum1 = 0.f;
#pragma unroll
        for (int na = 0; na < 4; na++) {
            sfrag[na][0] = __expf(sfrag[na][0] - mn0);
            sfrag[na][1] = __expf(sfrag[na][1] - mn0);
            sfrag[na][2] = __expf(sfrag[na][2] - mn1);
            sfrag[na][3] = __expf(sfrag[na][3] - mn1);
            sum0 += sfrag[na][0] + sfrag[na][1];
            sum1 += sfrag[na][2] + sfrag[na][3];
        }
        sum0 += __shfl_xor_sync(0xffffffffu, sum0, 1);
        sum0 += __shfl_xor_sync(0xffffffffu, sum0, 2);
        sum1 += __shfl_xor_sync(0xffffffffu, sum1, 1);
        sum1 += __shfl_xor_sync(0xffffffffu, sum1, 2);
        l0 = l0 * a0 + sum0;  m0 = mn0;
        l1 = l1 * a1 + sum1;  m1 = mn1;
#pragma unroll
        for (int na = 0; na < 8; na++) {
            o[na][0] *= a0; o[na][1] *= a0;
            o[na][2] *= a1; o[na][3] *= a1;
        }

        // ---- P (tf32) -> warp-private smem rows; __syncwarp suffices ----
        {
            const int pr0 = wid * 16 + g;
            const int kc  = 2 * tig;
#pragma unroll
            for (int na = 0; na < 4; na++) {
                *(float2*)&fsm[F_PS + pr0 * FP_STRIDE + na * 8 + kc] =
                    make_float2(to_tf32(sfrag[na][0]), to_tf32(sfrag[na][1]));
                *(float2*)&fsm[F_PS + (pr0 + 8) * FP_STRIDE + na * 8 + kc] =
                    make_float2(to_tf32(sfrag[na][2]), to_tf32(sfrag[na][3]));
            }
        }
        __syncwarp();

        // ---- O += P V : 4 ks (32 keys) x 8 na (64 d) ----
#pragma unroll
        for (int ks = 0; ks < 4; ks++) {
            uint32_t af[4];
            LDMATRIX_X4(af, p_lm + ks * 32);
#pragma unroll
            for (int na = 0; na < 8; na++) {
                uint32_t bf[2];
                bf[0] = __float_as_uint(Vs[(ks * 8 + tig) * FV_STRIDE + na * 8 + g]);
                bf[1] = __float_as_uint(Vs[(ks * 8 + tig + 4) * FV_STRIDE + na * 8 + g]);
                MMA_TF32(o[na], af, bf);
            }
        }
        // no bottom barrier: next iter's top barrier provides the ordering
    }

    // ---- epilogue: /l, tf32-round (A operand of out-proj), store ----
    const float i0 = 1.f / l0;
    const float i1 = 1.f / l1;
    const int r0 = q0 + wid * 16 + g;
    float* out0 = &g_attn[(size_t)(b * T_SEQ + r0) * D_MODEL + h * HEAD_DIM + 2 * tig];
    float* out1 = &g_attn[(size_t)(b * T_SEQ + r0 + 8) * D_MODEL + h * HEAD_DIM + 2 * tig];
#pragma unroll
    for (int na = 0; na < 8; na++) {
        *(float2*)&out0[na * 8] = make_float2(to_tf32(o[na][0] * i0), to_tf32(o[na][1] * i0));
        *(float2*)&out1[na * 8] = make_float2(to_tf32(o[na][2] * i1), to_tf32(o[na][3] * i1));
    }
}

// ---------------------------------------------------------------------------
// Launch
// ---------------------------------------------------------------------------
extern "C" void kernel_launch(void* const* d_in, const int* in_sizes, int n_in,
                              void* d_out, int out_size) {
    const float* x     = (const float*)d_in[0];   // [2,2048,1024]
    const float* w_qkv = (const float*)d_in[1];   // [1024,3072]
    const float* w_out = (const float*)d_in[2];   // [1024,1024]
    float* out = (float*)d_out;                   // [2,2048,1024]

    void *qkv_p, *attn_p, *xr_p, *wqkv_p, *wout_p;
    cudaGetSymbolAddress(&qkv_p,  g_qkv);
    cudaGetSymbolAddress(&attn_p, g_attn);
    cudaGetSymbolAddress(&xr_p,   g_xr);
    cudaGetSymbolAddress(&wqkv_p, g_wqkv_r);
    cudaGetSymbolAddress(&wout_p, g_wout_r);

    const int fa_smem = F_SMEM_FLOATS * (int)sizeof(float);    // 45056 B
    cudaFuncSetAttribute(flash_mma_kernel,
                         cudaFuncAttributeMaxDynamicSharedMemorySize, fa_smem);
    cudaFuncSetAttribute(gemm_mma_big<true>,
                         cudaFuncAttributeMaxDynamicSharedMemorySize, GB_SMEM_BYTES);
    cudaFuncSetAttribute(gemm_mma_big<false>,
                         cudaFuncAttributeMaxDynamicSharedMemorySize, GB_SMEM_BYTES);

    // 0) fused tf32 pre-round of all inputs
    round_all_kernel<<<(RN_TOTAL + 255) / 256, 256>>>(x, w_qkv, w_out);

    // 1) QKV projection (output tf32-rounded)
    gemm_mma_big<true><<<dim3(QKV_LD / 128, M_TOTAL / 256), 256, GB_SMEM_BYTES>>>(
        (const float*)xr_p, (const float*)wqkv_p, (float*)qkv_p,
        M_TOTAL, QKV_LD, D_MODEL);

    // 2) causal flash attention (4 CTAs/SM, single barrier per iteration)
    flash_mma_kernel<<<dim3(T_SEQ / 64, BATCH * N_HEADS), 128, fa_smem>>>();

    // 3) output projection
    gemm_mma_big<false><<<dim3(D_MODEL / 128, M_TOTAL / 256), 256, GB_SMEM_BYTES>>>(
        (const float*)attn_p, (const float*)wout_p, out,
        M_TOTAL, D_MODEL, D_MODEL);
}

// round 14
// speedup vs baseline: 1.3090x; 1.3090x over previous
#include <cuda_runtime.h>
#include <cuda_fp16.h>
#include <math.h>
#include <stdint.h>

// Problem constants
#define BATCH    2
#define T_SEQ    2048
#define D_MODEL  1024
#define N_HEADS  16
#define HEAD_DIM 64
#define M_TOTAL  (BATCH * T_SEQ)          // 4096 rows
#define QKV_LD   (3 * D_MODEL)            // 3072

// Scratch (allocation-free rule: __device__ globals)
__device__ float  g_qkv   [M_TOTAL * QKV_LD];    // [4096, 3072] tf32-rounded (QKV gemm out)
__device__ __half g_attnh [M_TOTAL * D_MODEL];   // [4096, 1024] fp16 (flash out = out-proj A)
__device__ __half g_xh    [M_TOTAL * D_MODEL];   // fp16 x
__device__ __half g_wqkvT [QKV_LD * D_MODEL];    // fp16 w_qkv^T  [3072][1024]
__device__ __half g_woutT [D_MODEL * D_MODEL];   // fp16 w_out^T  [1024][1024]

__device__ __forceinline__ float to_tf32(float x) {
    float y;
    asm("cvt.rna.tf32.f32 %0, %1;" : "=f"(y) : "f"(x));
    return y;
}
__device__ __forceinline__ uint32_t smem_u32(const void* p) {
    uint32_t a;
    asm("{ .reg .u64 t; cvta.to.shared.u64 t, %1; cvt.u32.u64 %0, t; }" : "=r"(a) : "l"(p));
    return a;
}
__device__ __forceinline__ void cp16(uint32_t dst, const void* src) {
    asm volatile("cp.async.cg.shared.global [%0], [%1], 16;" :: "r"(dst), "l"(src) : "memory");
}
#define MMA_TF32(D, A, B) \
    asm volatile("mma.sync.aligned.m16n8k8.row.col.f32.tf32.tf32.f32 " \
                 "{%0,%1,%2,%3}, {%4,%5,%6,%7}, {%8,%9}, {%0,%1,%2,%3};" \
                 : "+f"((D)[0]), "+f"((D)[1]), "+f"((D)[2]), "+f"((D)[3]) \
                 : "r"((A)[0]), "r"((A)[1]), "r"((A)[2]), "r"((A)[3]), \
                   "r"((B)[0]), "r"((B)[1]))
#define MMA_F16(D, A, B) \
    asm volatile("mma.sync.aligned.m16n8k16.row.col.f32.f16.f16.f32 " \
                 "{%0,%1,%2,%3}, {%4,%5,%6,%7}, {%8,%9}, {%0,%1,%2,%3};" \
                 : "+f"((D)[0]), "+f"((D)[1]), "+f"((D)[2]), "+f"((D)[3]) \
                 : "r"((A)[0]), "r"((A)[1]), "r"((A)[2]), "r"((A)[3]), \
                   "r"((B)[0]), "r"((B)[1]))
#define LDMATRIX_X4(R, ADDR) \
    asm volatile("ldmatrix.sync.aligned.m8n8.x4.shared.b16 {%0,%1,%2,%3}, [%4];" \
                 : "=r"((R)[0]), "=r"((R)[1]), "=r"((R)[2]), "=r"((R)[3]) : "r"(ADDR))

// ---------------------------------------------------------------------------
// fp16 mma.sync GEMM: C[M,N] = A[M,K] @ B_T[N,K]^T, fp32 accumulate.
// 128x128 block tile, 8 warps (2x4), warp tile 64x32 = 4 m-atoms x 4 n-atoms
// of m16n8k16. K-tile 64 (4 k-steps), 3-stage cp.async, 2 CTAs/SM.
// smem per stage: A [128][72 halves] (144 B rows = 9x16B, ldmatrix
// conflict-free) + B_T [128][72 halves] (B-frag LDS.32 banks 4g+tig distinct).
// B fragment b0 = {B_T[n][2tig], [2tig+1]} contiguous -> single LDS.32.
// ---------------------------------------------------------------------------
#define GH_ROW_B   144                            // bytes per smem row
#define GH_A_BYTES (128 * GH_ROW_B)               // 18432
#define GH_STAGE   (2 * GH_A_BYTES)               // 36864 B
#define GH_SMEM_BYTES (3 * GH_STAGE)              // 110592 B

__device__ __forceinline__ void issue_stage_h(uint32_t sb, const __half* __restrict__ A,
                                              const __half* __restrict__ BT,
                                              int tid, int row0, int col0, int k0, int K) {
#pragma unroll
    for (int i = 0; i < 4; i++) {
        int ff = tid + i * 256;                   // 1024 chunks each
        int r  = ff >> 3, c = ff & 7;             // row, 16B chunk (8 halves)
        cp16(sb + r * GH_ROW_B + c * 16, &A[(size_t)(row0 + r) * K + k0 + c * 8]);
        cp16(sb + GH_A_BYTES + r * GH_ROW_B + c * 16,
             &BT[(size_t)(col0 + r) * K + k0 + c * 8]);
    }
}

template <bool ROUND>
__global__ __launch_bounds__(256, 2) void gemm_h(const __half* __restrict__ A,
                                                 const __half* __restrict__ BT,
                                                 float* __restrict__ C,
                                                 int M, int N, int K) {
    extern __shared__ __align__(16) char gsm[];
    const uint32_t sb = smem_u32(gsm);
    const int tid  = threadIdx.x;
    const int lane = tid & 31;
    const int wid  = tid >> 5;
    const int wr = wid >> 2, wc = wid & 3;        // 2x4 warp grid
    const int g  = lane >> 2, tig = lane & 3;
    const int row0 = blockIdx.y * 128;
    const int col0 = blockIdx.x * 128;

    float d[4][4][4] = {};
    const int T = K >> 6;                         // K-tile 64

    issue_stage_h(sb + 0 * GH_STAGE, A, BT, tid, row0, col0, 0, K);
    asm volatile("cp.async.commit_group;" ::: "memory");
    issue_stage_h(sb + 1 * GH_STAGE, A, BT, tid, row0, col0, 64, K);
    asm volatile("cp.async.commit_group;" ::: "memory");

    // ldmatrix A base: row = wr*64 + ((lane>>3)&1)*8 + (lane&7), seg=(lane>>4)&1
    const uint32_t a_base = sb + (wr * 64 + ((lane >> 3) & 1) * 8 + (lane & 7)) * GH_ROW_B
                          + ((lane >> 4) & 1) * 16;

    for (int t = 0; t < T; t++) {
        const int s = t % 3;
        asm volatile("cp.async.wait_group 1;" ::: "memory");
        __syncthreads();

        const uint32_t aS = a_base + s * GH_STAGE;
        const uint32_t* sBu = (const uint32_t*)(gsm + s * GH_STAGE + GH_A_BYTES);

#pragma unroll
        for (int ks = 0; ks < 4; ks++) {          // k-step = 16 halves = 32 B
            uint32_t af[4][4], bf[4][2];
#pragma unroll
            for (int ma = 0; ma < 4; ma++)
                LDMATRIX_X4(af[ma], aS + ma * 16 * GH_ROW_B + ks * 32);
#pragma unroll
            for (int na = 0; na < 4; na++) {
                const int n = wc * 32 + na * 8 + g;
                bf[na][0] = sBu[n * 36 + ks * 8 + tig];       // halves 2tig,2tig+1
                bf[na][1] = sBu[n * 36 + ks * 8 + tig + 4];   // halves 2tig+8,+9
            }
#pragma unroll
            for (int ma = 0; ma < 4; ma++)
#pragma unroll
                for (int na = 0; na < 4; na++)
                    MMA_F16(d[ma][na], af[ma], bf[na]);
        }

        if (t + 2 < T)
            issue_stage_h(sb + ((t + 2) % 3) * GH_STAGE, A, BT, tid,
                          row0, col0, (t + 2) * 64, K);
        asm volatile("cp.async.commit_group;" ::: "memory");
    }

#pragma unroll
    for (int ma = 0; ma < 4; ma++)
#pragma unroll
        for (int na = 0; na < 4; na++) {
            const int r = row0 + wr * 64 + ma * 16 + g;
            const int c = col0 + wc * 32 + na * 8 + tig * 2;
            float4 v = make_float4(d[ma][na][0], d[ma][na][1], d[ma][na][2], d[ma][na][3]);
            if (ROUND) {
                v.x = to_tf32(v.x); v.y = to_tf32(v.y);
                v.z = to_tf32(v.z); v.w = to_tf32(v.w);
            }
            *(float2*)&C[(size_t)r * N + c]       = make_float2(v.x, v.y);
            *(float2*)&C[(size_t)(r + 8) * N + c] = make_float2(v.z, v.w);
        }
}

// ---------------------------------------------------------------------------
// Preprocessing: x -> fp16 (coalesced); w -> fp16 transposed [N][K]
// ---------------------------------------------------------------------------
__global__ void conv_x_kernel(const float* __restrict__ x, __half* __restrict__ xh, int n4) {
    int i = blockIdx.x * blockDim.x + threadIdx.x;
    if (i >= n4) return;
    float4 v = ((const float4*)x)[i];
    ((__half2*)xh)[2 * i]     = __floats2half2_rn(v.x, v.y);
    ((__half2*)xh)[2 * i + 1] = __floats2half2_rn(v.z, v.w);
}

__global__ void conv_T_kernel(const float* __restrict__ w, __half* __restrict__ wT,
                              int K, int N) {
    int i = blockIdx.x * blockDim.x + threadIdx.x;
    if (i >= (K * N) / 4) return;
    int n  = i % N;
    int k4 = (i / N) * 4;
    __half2 h0 = __floats2half2_rn(w[(size_t)(k4 + 0) * N + n], w[(size_t)(k4 + 1) * N + n]);
    __half2 h1 = __floats2half2_rn(w[(size_t)(k4 + 2) * N + n], w[(size_t)(k4 + 3) * N + n]);
    __half2* dst = (__half2*)&wT[(size_t)n * K + k4];
    dst[0] = h0;
    dst[1] = h1;
}

// ---------------------------------------------------------------------------
// Causal flash attention (tf32 mma.sync) — R12 config (4 CTAs/SM, single
// barrier per key-tile iteration, Q pre-scaled by 1/8). Epilogue now emits
// fp16 g_attnh (same 10-bit mantissa as the tf32 round it replaces).
// ---------------------------------------------------------------------------
#define FK_STRIDE 68
#define FV_STRIDE 72
#define FP_STRIDE 36
#define F_STAGE_FLOATS (32 * FK_STRIDE + 32 * FV_STRIDE)    // 4480
#define F_PS (2 * F_STAGE_FLOATS)                           // 8960
#define F_SMEM_FLOATS (F_PS + 64 * FP_STRIDE)               // 11264 fl = 45056 B

__global__ __launch_bounds__(128, 4) void flash_mma_kernel() {
    extern __shared__ __align__(16) float fsm[];
    const uint32_t sb = smem_u32(fsm);
    const int tid  = threadIdx.x;
    const int lane = tid & 31;
    const int wid  = tid >> 5;
    const int g    = lane >> 2;
    const int tig  = lane & 3;

    const int qt = (gridDim.x - 1) - blockIdx.x;
    const int bh = blockIdx.y;
    const int b  = bh >> 4;
    const int h  = bh & 15;
    const int q0 = qt * 64;

    const float* base = g_qkv + (size_t)b * T_SEQ * QKV_LD + h * HEAD_DIM;
    const float* Qg = base;
    const float* Kg = base + D_MODEL;
    const float* Vg = base + 2 * D_MODEL;

#pragma unroll
    for (int i = 0; i < 8; i++) {
        int ff = tid + i * 128;
        int r  = ff >> 4;
        int d4 = (ff & 15) * 4;
        cp16(sb + (r * FK_STRIDE + d4) * 4, &Qg[(size_t)(q0 + r) * QKV_LD + d4]);
    }
    asm volatile("cp.async.commit_group;" ::: "memory");
#pragma unroll
    for (int i = 0; i < 4; i++) {
        int ff = tid + i * 128;
        int r  = ff >> 4;
        int d4 = (ff & 15) * 4;
        const size_t grow = (size_t)r * QKV_LD + d4;
        cp16(sb + (F_STAGE_FLOATS + r * FK_STRIDE + d4) * 4, &Kg[grow]);
        cp16(sb + (F_STAGE_FLOATS + 32 * FK_STRIDE + r * FV_STRIDE + d4) * 4, &Vg[grow]);
    }
    asm volatile("cp.async.commit_group;" ::: "memory");
    asm volatile("cp.async.wait_group 1;" ::: "memory");
    __syncthreads();

    const int lm_rr  = ((lane >> 3) & 1) * 8 + (lane & 7);
    const int lm_col = ((lane >> 4) & 1) * 4;
    uint32_t qf[8][4];
    {
        const uint32_t q_lm = sb + ((wid * 16 + lm_rr) * FK_STRIDE + lm_col) * 4;
#pragma unroll
        for (int ks = 0; ks < 8; ks++) {
            LDMATRIX_X4(qf[ks], q_lm + ks * 32);
#pragma unroll
            for (int r = 0; r < 4; r++)
                qf[ks][r] = __float_as_uint(__uint_as_float(qf[ks][r]) * 0.125f);
        }
    }

    const uint32_t p_lm = sb + (F_PS + (wid * 16 + lm_rr) * FP_STRIDE + lm_col) * 4;

    const float NEG_INF = __int_as_float(0xff800000u);
    float o[8][4] = {};
    float m0 = NEG_INF, m1 = NEG_INF, l0 = 0.f, l1 = 0.f;

    const int nkt = 2 * qt + 2;
    for (int kt = 0; kt < nkt; kt++) {
        const int s = (kt + 1) & 1;

        asm volatile("cp.async.wait_group 0;" ::: "memory");
        __syncthreads();

        if (kt + 1 < nkt) {
            const int sd = kt & 1;
#pragma unroll
            for (int i = 0; i < 4; i++) {
                int ff = tid + i * 128;
                int r  = ff >> 4;
                int d4 = (ff & 15) * 4;
                const size_t grow = (size_t)((kt + 1) * 32 + r) * QKV_LD + d4;
                cp16(sb + (sd * F_STAGE_FLOATS + r * FK_STRIDE + d4) * 4, &Kg[grow]);
                cp16(sb + (sd * F_STAGE_FLOATS + 32 * FK_STRIDE + r * FV_STRIDE + d4) * 4,
                     &Vg[grow]);
            }
            asm volatile("cp.async.commit_group;" ::: "memory");
        }

        const float* Ks = fsm + s * F_STAGE_FLOATS;
        const float* Vs = Ks + 32 * FK_STRIDE;

        float sfrag[4][4] = {};
#pragma unroll
        for (int ks = 0; ks < 8; ks++) {
#pragma unroll
            for (int na = 0; na < 4; na++) {
                uint32_t bf[2];
                bf[0] = __float_as_uint(Ks[(na * 8 + g) * FK_STRIDE + ks * 8 + tig]);
                bf[1] = __float_as_uint(Ks[(na * 8 + g) * FK_STRIDE + ks * 8 + tig + 4]);
                MMA_TF32(sfrag[na], qf[ks], bf);
            }
        }

        const bool diag = (kt >= 2 * qt);
        const int qr0 = q0 + wid * 16 + g;
        const int qr1 = qr0 + 8;
        if (diag) {
#pragma unroll
            for (int na = 0; na < 4; na++) {
                const int kg = kt * 32 + na * 8 + 2 * tig;
                if (kg     > qr0) sfrag[na][0] = NEG_INF;
                if (kg + 1 > qr0) sfrag[na][1] = NEG_INF;
                if (kg     > qr1) sfrag[na][2] = NEG_INF;
                if (kg + 1 > qr1) sfrag[na][3] = NEG_INF;
            }
        }

        float mx0 = NEG_INF, mx1 = NEG_INF;
#pragma unroll
        for (int na = 0; na < 4; na++) {
            mx0 = fmaxf(mx0, fmaxf(sfrag[na][0], sfrag[na][1]));
            mx1 = fmaxf(mx1, fmaxf(sfrag[na][2], sfrag[na][3]));
        }
        mx0 = fmaxf(mx0, __shfl_xor_sync(0xffffffffu, mx0, 1));
        mx0 = fmaxf(mx0, __shfl_xor_sync(0xffffffffu, mx0, 2));
        mx1 = fmaxf(mx1, __shfl_xor_sync(0xffffffffu, mx1, 1));
        mx1 = fmaxf(mx1, __shfl_xor_sync(0xffffffffu, mx1, 2));
        const float mn0 = fmaxf(m0, mx0);
        const float mn1 = fmaxf(m1, mx1);
        const float a0 = __expf(m0 - mn0);
        const float a1 = __expf(m1 - mn1);
        float sum0 = 0.f, sum1 = 0.f;
#pragma unroll
        for (int na = 0; na < 4; na++) {
            sfrag[na][0] = __expf(sfrag[na][0] - mn0);
            sfrag[na][1] = __expf(sfrag[na][1] - mn0);
            sfrag[na][2] = __expf(sfrag[na][2] - mn1);
            sfrag[na][3] = __expf(sfrag[na][3] - mn1);
            sum0 += sfrag[na][0] + sfrag[na][1];
            sum1 += sfrag[na][2] + sfrag[na][3];
        }
        sum0 += __shfl_xor_sync(0xffffffffu, sum0, 1);
        sum0 += __shfl_xor_sync(0xffffffffu, sum0, 2);
        sum1 += __shfl_xor_sync(0xffffffffu, sum1, 1);
        sum1 += __shfl_xor_sync(0xffffffffu, sum1, 2);
        l0 = l0 * a0 + sum0;  m0 = mn0;
        l1 = l1 * a1 + sum1;  m1 = mn1;
#pragma unroll
        for (int na = 0; na < 8; na++) {
            o[na][0] *= a0; o[na][1] *= a0;
            o[na][2] *= a1; o[na][3] *= a1;
        }

        {
            const int pr0 = wid * 16 + g;
            const int kc  = 2 * tig;
#pragma unroll
            for (int na = 0; na < 4; na++) {
                *(float2*)&fsm[F_PS + pr0 * FP_STRIDE + na * 8 + kc] =
                    make_float2(to_tf32(sfrag[na][0]), to_tf32(sfrag[na][1]));
                *(float2*)&fsm[F_PS + (pr0 + 8) * FP_STRIDE + na * 8 + kc] =
                    make_float2(to_tf32(sfrag[na][2]), to_tf32(sfrag[na][3]));
            }
        }
        __syncwarp();

#pragma unroll
        for (int ks = 0; ks < 4; ks++) {
            uint32_t af[4];
            LDMATRIX_X4(af, p_lm + ks * 32);
#pragma unroll
            for (int na = 0; na < 8; na++) {
                uint32_t bf[2];
                bf[0] = __float_as_uint(Vs[(ks * 8 + tig) * FV_STRIDE + na * 8 + g]);
                bf[1] = __float_as_uint(Vs[(ks * 8 + tig + 4) * FV_STRIDE + na * 8 + g]);
                MMA_TF32(o[na], af, bf);
            }
        }
    }

    // ---- epilogue: /l, fp16 (A operand of fp16 out-proj), store ----
    const float i0 = 1.f / l0;
    const float i1 = 1.f / l1;
    const int r0 = q0 + wid * 16 + g;
    __half* out0 = &g_attnh[(size_t)(b * T_SEQ + r0) * D_MODEL + h * HEAD_DIM + 2 * tig];
    __half* out1 = &g_attnh[(size_t)(b * T_SEQ + r0 + 8) * D_MODEL + h * HEAD_DIM + 2 * tig];
#pragma unroll
    for (int na = 0; na < 8; na++) {
        *(__half2*)&out0[na * 8] = __floats2half2_rn(o[na][0] * i0, o[na][1] * i0);
        *(__half2*)&out1[na * 8] = __floats2half2_rn(o[na][2] * i1, o[na][3] * i1);
    }
}

// ---------------------------------------------------------------------------
// Launch
// ---------------------------------------------------------------------------
extern "C" void kernel_launch(void* const* d_in, const int* in_sizes, int n_in,
                              void* d_out, int out_size) {
    const float* x     = (const float*)d_in[0];   // [2,2048,1024]
    const float* w_qkv = (const float*)d_in[1];   // [1024,3072]
    const float* w_out = (const float*)d_in[2];   // [1024,1024]
    float* out = (float*)d_out;                   // [2,2048,1024]

    void *qkv_p, *attnh_p, *xh_p, *wqkvT_p, *woutT_p;
    cudaGetSymbolAddress(&qkv_p,   g_qkv);
    cudaGetSymbolAddress(&attnh_p, g_attnh);
    cudaGetSymbolAddress(&xh_p,    g_xh);
    cudaGetSymbolAddress(&wqkvT_p, g_wqkvT);
    cudaGetSymbolAddress(&woutT_p, g_woutT);

    const int fa_smem = F_SMEM_FLOATS * (int)sizeof(float);    // 45056 B
    cudaFuncSetAttribute(flash_mma_kernel,
                         cudaFuncAttributeMaxDynamicSharedMemorySize, fa_smem);
    cudaFuncSetAttribute(gemm_h<true>,
                         cudaFuncAttributeMaxDynamicSharedMemorySize, GH_SMEM_BYTES);
    cudaFuncSetAttribute(gemm_h<false>,
                         cudaFuncAttributeMaxDynamicSharedMemorySize, GH_SMEM_BYTES);

    // 0) preprocess: x -> fp16; weights -> fp16 transposed
    {
        int n4 = M_TOTAL * D_MODEL / 4;
        conv_x_kernel<<<(n4 + 255) / 256, 256>>>(x, (__half*)xh_p, n4);
        int nt = D_MODEL * QKV_LD / 4;
        conv_T_kernel<<<(nt + 255) / 256, 256>>>(w_qkv, (__half*)wqkvT_p, D_MODEL, QKV_LD);
        nt = D_MODEL * D_MODEL / 4;
        conv_T_kernel<<<(nt + 255) / 256, 256>>>(w_out, (__half*)woutT_p, D_MODEL, D_MODEL);
    }

    // 1) QKV projection (fp16 mma, output tf32-rounded fp32 for flash)
    gemm_h<true><<<dim3(QKV_LD / 128, M_TOTAL / 128), 256, GH_SMEM_BYTES>>>(
        (const __half*)xh_p, (const __half*)wqkvT_p, (float*)qkv_p,
        M_TOTAL, QKV_LD, D_MODEL);

    // 2) causal flash attention (tf32, 4 CTAs/SM, single barrier/iter)
    flash_mma_kernel<<<dim3(T_SEQ / 64, BATCH * N_HEADS), 128, fa_smem>>>();

    // 3) output projection (fp16 mma)
    gemm_h<false><<<dim3(D_MODEL / 128, M_TOTAL / 128), 256, GH_SMEM_BYTES>>>(
        (const __half*)attnh_p, (const __half*)woutT_p, out,
        M_TOTAL, D_MODEL, D_MODEL);
}

// round 15
// speedup vs baseline: 1.7445x; 1.3326x over previous
#include <cuda_runtime.h>
#include <cuda_fp16.h>
#include <math.h>
#include <stdint.h>

// Problem constants
#define BATCH    2
#define T_SEQ    2048
#define D_MODEL  1024
#define N_HEADS  16
#define HEAD_DIM 64
#define M_TOTAL  (BATCH * T_SEQ)          // 4096 rows
#define QKV_LD   (3 * D_MODEL)            // 3072

// Scratch (allocation-free rule: __device__ globals)
__device__ __half g_qkvh  [M_TOTAL * QKV_LD];    // [4096, 3072] fp16 QKV
__device__ __half g_attnh [M_TOTAL * D_MODEL];   // [4096, 1024] fp16 attention out
__device__ __half g_xh    [M_TOTAL * D_MODEL];   // fp16 x
__device__ __half g_wqkvT [QKV_LD * D_MODEL];    // fp16 w_qkv^T  [3072][1024]
__device__ __half g_woutT [D_MODEL * D_MODEL];   // fp16 w_out^T  [1024][1024]

__device__ __forceinline__ uint32_t smem_u32(const void* p) {
    uint32_t a;
    asm("{ .reg .u64 t; cvta.to.shared.u64 t, %1; cvt.u32.u64 %0, t; }" : "=r"(a) : "l"(p));
    return a;
}
__device__ __forceinline__ void cp16(uint32_t dst, const void* src) {
    asm volatile("cp.async.cg.shared.global [%0], [%1], 16;" :: "r"(dst), "l"(src) : "memory");
}
#define MMA_F16(D, A, B) \
    asm volatile("mma.sync.aligned.m16n8k16.row.col.f32.f16.f16.f32 " \
                 "{%0,%1,%2,%3}, {%4,%5,%6,%7}, {%8,%9}, {%0,%1,%2,%3};" \
                 : "+f"((D)[0]), "+f"((D)[1]), "+f"((D)[2]), "+f"((D)[3]) \
                 : "r"((A)[0]), "r"((A)[1]), "r"((A)[2]), "r"((A)[3]), \
                   "r"((B)[0]), "r"((B)[1]))
#define LDMATRIX_X4(R, ADDR) \
    asm volatile("ldmatrix.sync.aligned.m8n8.x4.shared.b16 {%0,%1,%2,%3}, [%4];" \
                 : "=r"((R)[0]), "=r"((R)[1]), "=r"((R)[2]), "=r"((R)[3]) : "r"(ADDR))
#define LDMATRIX_X4_T(R, ADDR) \
    asm volatile("ldmatrix.sync.aligned.m8n8.x4.trans.shared.b16 {%0,%1,%2,%3}, [%4];" \
                 : "=r"((R)[0]), "=r"((R)[1]), "=r"((R)[2]), "=r"((R)[3]) : "r"(ADDR))

// ---------------------------------------------------------------------------
// fp16 mma.sync GEMM: C[M,N] = A[M,K] @ B_T[N,K]^T, fp32 accumulate.
// 128x128 block, 8 warps (2x4), warp 64x32 = 4x4 m16n8k16 atoms, K-tile 64,
// 3-stage cp.async, 2 CTAs/SM. HALF_OUT selects fp16 vs fp32 output.
// ---------------------------------------------------------------------------
#define GH_ROW_B   144
#define GH_A_BYTES (128 * GH_ROW_B)
#define GH_STAGE   (2 * GH_A_BYTES)               // 36864 B
#define GH_SMEM_BYTES (3 * GH_STAGE)              // 110592 B

__device__ __forceinline__ void issue_stage_h(uint32_t sb, const __half* __restrict__ A,
                                              const __half* __restrict__ BT,
                                              int tid, int row0, int col0, int k0, int K) {
#pragma unroll
    for (int i = 0; i < 4; i++) {
        int ff = tid + i * 256;
        int r  = ff >> 3, c = ff & 7;
        cp16(sb + r * GH_ROW_B + c * 16, &A[(size_t)(row0 + r) * K + k0 + c * 8]);
        cp16(sb + GH_A_BYTES + r * GH_ROW_B + c * 16,
             &BT[(size_t)(col0 + r) * K + k0 + c * 8]);
    }
}

template <bool HALF_OUT>
__global__ __launch_bounds__(256, 2) void gemm_h(const __half* __restrict__ A,
                                                 const __half* __restrict__ BT,
                                                 void* __restrict__ Cv,
                                                 int M, int N, int K) {
    extern __shared__ __align__(16) char gsm[];
    const uint32_t sb = smem_u32(gsm);
    const int tid  = threadIdx.x;
    const int lane = tid & 31;
    const int wid  = tid >> 5;
    const int wr = wid >> 2, wc = wid & 3;
    const int g  = lane >> 2, tig = lane & 3;
    const int row0 = blockIdx.y * 128;
    const int col0 = blockIdx.x * 128;

    float d[4][4][4] = {};
    const int T = K >> 6;

    issue_stage_h(sb + 0 * GH_STAGE, A, BT, tid, row0, col0, 0, K);
    asm volatile("cp.async.commit_group;" ::: "memory");
    issue_stage_h(sb + 1 * GH_STAGE, A, BT, tid, row0, col0, 64, K);
    asm volatile("cp.async.commit_group;" ::: "memory");

    const uint32_t a_base = sb + (wr * 64 + ((lane >> 3) & 1) * 8 + (lane & 7)) * GH_ROW_B
                          + ((lane >> 4) & 1) * 16;

    for (int t = 0; t < T; t++) {
        const int s = t % 3;
        asm volatile("cp.async.wait_group 1;" ::: "memory");
        __syncthreads();

        const uint32_t aS = a_base + s * GH_STAGE;
        const uint32_t* sBu = (const uint32_t*)(gsm + s * GH_STAGE + GH_A_BYTES);

#pragma unroll
        for (int ks = 0; ks < 4; ks++) {
            uint32_t af[4][4], bf[4][2];
#pragma unroll
            for (int ma = 0; ma < 4; ma++)
                LDMATRIX_X4(af[ma], aS + ma * 16 * GH_ROW_B + ks * 32);
#pragma unroll
            for (int na = 0; na < 4; na++) {
                const int n = wc * 32 + na * 8 + g;
                bf[na][0] = sBu[n * 36 + ks * 8 + tig];
                bf[na][1] = sBu[n * 36 + ks * 8 + tig + 4];
            }
#pragma unroll
            for (int ma = 0; ma < 4; ma++)
#pragma unroll
                for (int na = 0; na < 4; na++)
                    MMA_F16(d[ma][na], af[ma], bf[na]);
        }

        if (t + 2 < T)
            issue_stage_h(sb + ((t + 2) % 3) * GH_STAGE, A, BT, tid,
                          row0, col0, (t + 2) * 64, K);
        asm volatile("cp.async.commit_group;" ::: "memory");
    }

#pragma unroll
    for (int ma = 0; ma < 4; ma++)
#pragma unroll
        for (int na = 0; na < 4; na++) {
            const int r = row0 + wr * 64 + ma * 16 + g;
            const int c = col0 + wc * 32 + na * 8 + tig * 2;
            if (HALF_OUT) {
                __half* C = (__half*)Cv;
                *(__half2*)&C[(size_t)r * N + c] =
                    __floats2half2_rn(d[ma][na][0], d[ma][na][1]);
                *(__half2*)&C[(size_t)(r + 8) * N + c] =
                    __floats2half2_rn(d[ma][na][2], d[ma][na][3]);
            } else {
                float* C = (float*)Cv;
                *(float2*)&C[(size_t)r * N + c]       = make_float2(d[ma][na][0], d[ma][na][1]);
                *(float2*)&C[(size_t)(r + 8) * N + c] = make_float2(d[ma][na][2], d[ma][na][3]);
            }
        }
}

// ---------------------------------------------------------------------------
// Preprocessing: x -> fp16 (coalesced); w -> fp16 transposed [N][K]
// ---------------------------------------------------------------------------
__global__ void conv_x_kernel(const float* __restrict__ x, __half* __restrict__ xh, int n4) {
    int i = blockIdx.x * blockDim.x + threadIdx.x;
    if (i >= n4) return;
    float4 v = ((const float4*)x)[i];
    ((__half2*)xh)[2 * i]     = __floats2half2_rn(v.x, v.y);
    ((__half2*)xh)[2 * i + 1] = __floats2half2_rn(v.z, v.w);
}

__global__ void conv_T_kernel(const float* __restrict__ w, __half* __restrict__ wT,
                              int K, int N) {
    int i = blockIdx.x * blockDim.x + threadIdx.x;
    if (i >= (K * N) / 4) return;
    int n  = i % N;
    int k4 = (i / N) * 4;
    __half2 h0 = __floats2half2_rn(w[(size_t)(k4 + 0) * N + n], w[(size_t)(k4 + 1) * N + n]);
    __half2 h1 = __floats2half2_rn(w[(size_t)(k4 + 2) * N + n], w[(size_t)(k4 + 3) * N + n]);
    __half2* dst = (__half2*)&wT[(size_t)n * K + k4];
    dst[0] = h0;
    dst[1] = h1;
}

// ---------------------------------------------------------------------------
// Causal flash attention — fp16 mma (m16n8k16), fp32 softmax/accumulators.
// R12 skeleton: 4 CTAs/SM, 64-q tiles, 32-key tiles, single barrier/iter,
// double-buffered KV cp.async, Q fragments hoisted (and pre-scaled by 1/8).
// S: K natural [key][d] -> B frags are contiguous half-pairs (LDS.32,
//    banks 4g+tig distinct at 72-half stride).
// PV: V natural [key][d] -> B frags via ldmatrix.x4.trans (phases (k+c)%8).
// P: fp16 [64][40 halves] (80 B = 5x16B rows, ldmatrix phases 5r%8 distinct).
// ---------------------------------------------------------------------------
#define FH_ROW    144                                // K/V/Q row bytes (72 halves)
#define FH_HALF_STAGE 4608                           // 32 rows * 144
#define FH_STAGE  (2 * FH_HALF_STAGE)                // 9216 B (K + V)
#define FH_PS     (2 * FH_STAGE)                     // 18432
#define FH_P_ROW  80
#define FH_SMEM_BYTES (FH_PS + 64 * FH_P_ROW)        // 23552 B

__global__ __launch_bounds__(128, 4) void flash_h_kernel() {
    extern __shared__ __align__(16) char fsmc[];
    const uint32_t sb = smem_u32(fsmc);
    const int tid  = threadIdx.x;
    const int lane = tid & 31;
    const int wid  = tid >> 5;        // warp owns q rows [16wid, 16wid+16)
    const int g    = lane >> 2;
    const int tig  = lane & 3;

    const int qt = (gridDim.x - 1) - blockIdx.x;     // reversed: heavy first
    const int bh = blockIdx.y;
    const int b  = bh >> 4;
    const int h  = bh & 15;
    const int q0 = qt * 64;

    const __half* base = g_qkvh + (size_t)b * T_SEQ * QKV_LD + h * HEAD_DIM;
    const __half* Qg = base;
    const __half* Kg = base + D_MODEL;
    const __half* Vg = base + 2 * D_MODEL;

    // ---- prologue: Q (64x64 halves) -> stage-0 region; KV(0) -> stage 1 ----
#pragma unroll
    for (int i = 0; i < 4; i++) {
        int ff = tid + i * 128;       // 0..511 chunks (16B = 8 halves)
        int r  = ff >> 3;             // q row 0..63
        int c  = ff & 7;
        cp16(sb + r * FH_ROW + c * 16, &Qg[(size_t)(q0 + r) * QKV_LD + c * 8]);
    }
    asm volatile("cp.async.commit_group;" ::: "memory");
#pragma unroll
    for (int i = 0; i < 2; i++) {
        int ff = tid + i * 128;       // 0..255 : K rows 0..31
        int r  = ff >> 3, c = ff & 7;
        cp16(sb + FH_STAGE + r * FH_ROW + c * 16, &Kg[(size_t)r * QKV_LD + c * 8]);
    }
#pragma unroll
    for (int i = 0; i < 2; i++) {
        int ff = tid + i * 128;
        int r  = ff >> 3, c = ff & 7;
        cp16(sb + FH_STAGE + FH_HALF_STAGE + r * FH_ROW + c * 16,
             &Vg[(size_t)r * QKV_LD + c * 8]);
    }
    asm volatile("cp.async.commit_group;" ::: "memory");
    asm volatile("cp.async.wait_group 1;" ::: "memory");   // Q complete
    __syncthreads();

    // ---- Q fragments (4 ks of k=16), pre-scaled by 1/8 (exact in fp16) ----
    const int a_row = wid * 16 + ((lane >> 3) & 1) * 8 + (lane & 7);
    const int a_seg = (lane >> 4) & 1;
    uint32_t qf[4][4];
    {
        const __half2 sc = __float2half2_rn(0.125f);
        const uint32_t q_lm = sb + a_row * FH_ROW + a_seg * 16;
#pragma unroll
        for (int ks = 0; ks < 4; ks++) {
            LDMATRIX_X4(qf[ks], q_lm + ks * 32);
#pragma unroll
            for (int r = 0; r < 4; r++) {
                __half2 hv = *reinterpret_cast<__half2*>(&qf[ks][r]);
                hv = __hmul2(hv, sc);
                qf[ks][r] = *reinterpret_cast<uint32_t*>(&hv);
            }
        }
    }
    // no barrier: iter-0's top barrier orders extraction vs stage-0 overwrite

    const uint32_t p_lm = sb + FH_PS + a_row * FH_P_ROW + a_seg * 16;
    // V ldmatrix.trans per-lane offset (within Vs region)
    const uint32_t v_off = ((lane & 7) + ((lane >> 3) & 1) * 8) * FH_ROW
                         + ((lane >> 4) & 1) * 16;

    const float NEG_INF = __int_as_float(0xff800000u);
    float o[8][4] = {};
    float m0 = NEG_INF, m1 = NEG_INF, l0 = 0.f, l1 = 0.f;

    const int nkt = 2 * qt + 2;                       // 32-key tiles
    for (int kt = 0; kt < nkt; kt++) {
        const int s = (kt + 1) & 1;                   // stage holding KV(kt)

        asm volatile("cp.async.wait_group 0;" ::: "memory");
        __syncthreads();          // (a) KV(kt) visible; (b) stage (kt&1) free

        // prefetch KV(kt+1) into the stage just freed
        if (kt + 1 < nkt) {
            const int sd = kt & 1;
            const size_t krow0 = (size_t)(kt + 1) * 32;
#pragma unroll
            for (int i = 0; i < 2; i++) {
                int ff = tid + i * 128;
                int r  = ff >> 3, c = ff & 7;
                cp16(sb + sd * FH_STAGE + r * FH_ROW + c * 16,
                     &Kg[(krow0 + r) * QKV_LD + c * 8]);
            }
#pragma unroll
            for (int i = 0; i < 2; i++) {
                int ff = tid + i * 128;
                int r  = ff >> 3, c = ff & 7;
                cp16(sb + sd * FH_STAGE + FH_HALF_STAGE + r * FH_ROW + c * 16,
                     &Vg[(krow0 + r) * QKV_LD + c * 8]);
            }
            asm volatile("cp.async.commit_group;" ::: "memory");
        }

        const uint32_t* Ku = (const uint32_t*)(fsmc + s * FH_STAGE);
        const uint32_t vS  = sb + s * FH_STAGE + FH_HALF_STAGE;

        // ---- S = Q K^T : 4 ks (k=16) x 4 na (32 keys) ----
        float sfrag[4][4] = {};
#pragma unroll
        for (int ks = 0; ks < 4; ks++) {
#pragma unroll
            for (int na = 0; na < 4; na++) {
                uint32_t bf[2];
                bf[0] = Ku[(na * 8 + g) * 36 + ks * 8 + tig];
                bf[1] = Ku[(na * 8 + g) * 36 + ks * 8 + tig + 4];
                MMA_F16(sfrag[na], qf[ks], bf);
            }
        }

        // ---- causal mask (scores pre-scaled via Q) ----
        const bool diag = (kt >= 2 * qt);
        const int qr0 = q0 + wid * 16 + g;
        const int qr1 = qr0 + 8;
        if (diag) {
#pragma unroll
            for (int na = 0; na < 4; na++) {
                const int kg = kt * 32 + na * 8 + 2 * tig;
                if (kg     > qr0) sfrag[na][0] = NEG_INF;
                if (kg + 1 > qr0) sfrag[na][1] = NEG_INF;
                if (kg     > qr1) sfrag[na][2] = NEG_INF;
                if (kg + 1 > qr1) sfrag[na][3] = NEG_INF;
            }
        }

        // ---- online softmax (rows g / g+8; reduce across quad tig) ----
        float mx0 = NEG_INF, mx1 = NEG_INF;
#pragma unroll
        for (int na = 0; na < 4; na++) {
            mx0 = fmaxf(mx0, fmaxf(sfrag[na][0], sfrag[na][1]));
            mx1 = fmaxf(mx1, fmaxf(sfrag[na][2], sfrag[na][3]));
        }
        mx0 = fmaxf(mx0, __shfl_xor_sync(0xffffffffu, mx0, 1));
        mx0 = fmaxf(mx0, __shfl_xor_sync(0xffffffffu, mx0, 2));
        mx1 = fmaxf(mx1, __shfl_xor_sync(0xffffffffu, mx1, 1));
        mx1 = fmaxf(mx1, __shfl_xor_sync(0xffffffffu, mx1, 2));
        const float mn0 = fmaxf(m0, mx0);
        const float mn1 = fmaxf(m1, mx1);
        const float a0 = __expf(m0 - mn0);
        const float a1 = __expf(m1 - mn1);
        float sum0 = 0.f, sum1 = 0.f;
#pragma unroll
        for (int na = 0; na < 4; na++) {
            sfrag[na][0] = __expf(sfrag[na][0] - mn0);
            sfrag[na][1] = __expf(sfrag[na][1] - mn0);
            sfrag[na][2] = __expf(sfrag[na][2] - mn1);
            sfrag[na][3] = __expf(sfrag[na][3] - mn1);
            sum0 += sfrag[na][0] + sfrag[na][1];
            sum1 += sfrag[na][2] + sfrag[na][3];
        }
        sum0 += __shfl_xor_sync(0xffffffffu, sum0, 1);
        sum0 += __shfl_xor_sync(0xffffffffu, sum0, 2);
        sum1 += __shfl_xor_sync(0xffffffffu, sum1, 1);
        sum1 += __shfl_xor_sync(0xffffffffu, sum1, 2);
        l0 = l0 * a0 + sum0;  m0 = mn0;
        l1 = l1 * a1 + sum1;  m1 = mn1;
#pragma unroll
        for (int na = 0; na < 8; na++) {
            o[na][0] *= a0; o[na][1] *= a0;
            o[na][2] *= a1; o[na][3] *= a1;
        }

        // ---- P (fp16) -> warp-private smem rows; __syncwarp suffices ----
        {
            const int pr0 = wid * 16 + g;
#pragma unroll
            for (int na = 0; na < 4; na++) {
                *(__half2*)(fsmc + FH_PS + pr0 * FH_P_ROW + (na * 8 + 2 * tig) * 2) =
                    __floats2half2_rn(sfrag[na][0], sfrag[na][1]);
                *(__half2*)(fsmc + FH_PS + (pr0 + 8) * FH_P_ROW + (na * 8 + 2 * tig) * 2) =
                    __floats2half2_rn(sfrag[na][2], sfrag[na][3]);
            }
        }
        __syncwarp();

        // ---- O += P V : 2 ks (k=16 keys) x 8 na (64 d) via ldmatrix.trans ----
#pragma unroll
        for (int ks = 0; ks < 2; ks++) {
            uint32_t pf[4];
            LDMATRIX_X4(pf, p_lm + ks * 32);
#pragma unroll
            for (int np = 0; np < 4; np++) {         // na pairs (0,1)..(6,7)
                uint32_t vf[4];
                LDMATRIX_X4_T(vf, vS + v_off + ks * 16 * FH_ROW + np * 32);
                MMA_F16(o[np * 2],     pf, vf);      // bf = {vf[0], vf[1]}
                MMA_F16(o[np * 2 + 1], pf, vf + 2);  // bf = {vf[2], vf[3]}
            }
        }
        // no bottom barrier: next iter's top barrier provides the ordering
    }

    // ---- epilogue: /l, fp16 (A operand of fp16 out-proj), store ----
    const float i0 = 1.f / l0;
    const float i1 = 1.f / l1;
    const int r0 = q0 + wid * 16 + g;
    __half* out0 = &g_attnh[(size_t)(b * T_SEQ + r0) * D_MODEL + h * HEAD_DIM + 2 * tig];
    __half* out1 = &g_attnh[(size_t)(b * T_SEQ + r0 + 8) * D_MODEL + h * HEAD_DIM + 2 * tig];
#pragma unroll
    for (int na = 0; na < 8; na++) {
        *(__half2*)&out0[na * 8] = __floats2half2_rn(o[na][0] * i0, o[na][1] * i0);
        *(__half2*)&out1[na * 8] = __floats2half2_rn(o[na][2] * i1, o[na][3] * i1);
    }
}

// ---------------------------------------------------------------------------
// Launch
// ---------------------------------------------------------------------------
extern "C" void kernel_launch(void* const* d_in, const int* in_sizes, int n_in,
                              void* d_out, int out_size) {
    const float* x     = (const float*)d_in[0];   // [2,2048,1024]
    const float* w_qkv = (const float*)d_in[1];   // [1024,3072]
    const float* w_out = (const float*)d_in[2];   // [1024,1024]
    float* out = (float*)d_out;                   // [2,2048,1024]

    void *qkvh_p, *attnh_p, *xh_p, *wqkvT_p, *woutT_p;
    cudaGetSymbolAddress(&qkvh_p,  g_qkvh);
    cudaGetSymbolAddress(&attnh_p, g_attnh);
    cudaGetSymbolAddress(&xh_p,    g_xh);
    cudaGetSymbolAddress(&wqkvT_p, g_wqkvT);
    cudaGetSymbolAddress(&woutT_p, g_woutT);

    cudaFuncSetAttribute(flash_h_kernel,
                         cudaFuncAttributeMaxDynamicSharedMemorySize, FH_SMEM_BYTES);
    cudaFuncSetAttribute(gemm_h<true>,
                         cudaFuncAttributeMaxDynamicSharedMemorySize, GH_SMEM_BYTES);
    cudaFuncSetAttribute(gemm_h<false>,
                         cudaFuncAttributeMaxDynamicSharedMemorySize, GH_SMEM_BYTES);

    // 0) preprocess: x -> fp16; weights -> fp16 transposed
    {
        int n4 = M_TOTAL * D_MODEL / 4;
        conv_x_kernel<<<(n4 + 255) / 256, 256>>>(x, (__half*)xh_p, n4);
        int nt = D_MODEL * QKV_LD / 4;
        conv_T_kernel<<<(nt + 255) / 256, 256>>>(w_qkv, (__half*)wqkvT_p, D_MODEL, QKV_LD);
        nt = D_MODEL * D_MODEL / 4;
        conv_T_kernel<<<(nt + 255) / 256, 256>>>(w_out, (__half*)woutT_p, D_MODEL, D_MODEL);
    }

    // 1) QKV projection (fp16 mma, fp16 output for flash)
    gemm_h<true><<<dim3(QKV_LD / 128, M_TOTAL / 128), 256, GH_SMEM_BYTES>>>(
        (const __half*)xh_p, (const __half*)wqkvT_p, qkvh_p,
        M_TOTAL, QKV_LD, D_MODEL);

    // 2) causal flash attention (fp16 mma, 4 CTAs/SM, 1 barrier/iter)
    flash_h_kernel<<<dim3(T_SEQ / 64, BATCH * N_HEADS), 128, FH_SMEM_BYTES>>>();

    // 3) output projection (fp16 mma, fp32 output)
    gemm_h<false><<<dim3(D_MODEL / 128, M_TOTAL / 128), 256, GH_SMEM_BYTES>>>(
        (const __half*)attnh_p, (const __half*)woutT_p, out,
        M_TOTAL, D_MODEL, D_MODEL);
}

// round 16
// speedup vs baseline: 1.8078x; 1.0363x over previous
#include <cuda_runtime.h>
#include <cuda_fp16.h>
#include <math.h>
#include <stdint.h>

// Problem constants
#define BATCH    2
#define T_SEQ    2048
#define D_MODEL  1024
#define N_HEADS  16
#define HEAD_DIM 64
#define M_TOTAL  (BATCH * T_SEQ)          // 4096 rows
#define QKV_LD   (3 * D_MODEL)            // 3072

// Scratch (allocation-free rule: __device__ globals)
__device__ __half g_qkvh  [M_TOTAL * QKV_LD];    // [4096, 3072] fp16 QKV
__device__ __half g_attnh [M_TOTAL * D_MODEL];   // [4096, 1024] fp16 attention out
__device__ __half g_xh    [M_TOTAL * D_MODEL];   // fp16 x
__device__ __half g_wqkvT [QKV_LD * D_MODEL];    // fp16 w_qkv^T  [3072][1024]
__device__ __half g_woutT [D_MODEL * D_MODEL];   // fp16 w_out^T  [1024][1024]

__device__ __forceinline__ uint32_t smem_u32(const void* p) {
    uint32_t a;
    asm("{ .reg .u64 t; cvta.to.shared.u64 t, %1; cvt.u32.u64 %0, t; }" : "=r"(a) : "l"(p));
    return a;
}
__device__ __forceinline__ void cp16(uint32_t dst, const void* src) {
    asm volatile("cp.async.cg.shared.global [%0], [%1], 16;" :: "r"(dst), "l"(src) : "memory");
}
#define MMA_F16(D, A, B) \
    asm volatile("mma.sync.aligned.m16n8k16.row.col.f32.f16.f16.f32 " \
                 "{%0,%1,%2,%3}, {%4,%5,%6,%7}, {%8,%9}, {%0,%1,%2,%3};" \
                 : "+f"((D)[0]), "+f"((D)[1]), "+f"((D)[2]), "+f"((D)[3]) \
                 : "r"((A)[0]), "r"((A)[1]), "r"((A)[2]), "r"((A)[3]), \
                   "r"((B)[0]), "r"((B)[1]))
#define LDMATRIX_X4(R, ADDR) \
    asm volatile("ldmatrix.sync.aligned.m8n8.x4.shared.b16 {%0,%1,%2,%3}, [%4];" \
                 : "=r"((R)[0]), "=r"((R)[1]), "=r"((R)[2]), "=r"((R)[3]) : "r"(ADDR))
#define LDMATRIX_X4_T(R, ADDR) \
    asm volatile("ldmatrix.sync.aligned.m8n8.x4.trans.shared.b16 {%0,%1,%2,%3}, [%4];" \
                 : "=r"((R)[0]), "=r"((R)[1]), "=r"((R)[2]), "=r"((R)[3]) : "r"(ADDR))

// ---------------------------------------------------------------------------
// fp16 mma.sync GEMM (R15, validated): C[M,N] = A[M,K] @ B_T[N,K]^T, fp32 acc.
// 128x128 block, 8 warps (2x4), warp 64x32, K-tile 64, 3-stage cp.async.
// ---------------------------------------------------------------------------
#define GH_ROW_B   144
#define GH_A_BYTES (128 * GH_ROW_B)
#define GH_STAGE   (2 * GH_A_BYTES)               // 36864 B
#define GH_SMEM_BYTES (3 * GH_STAGE)              // 110592 B

__device__ __forceinline__ void issue_stage_h(uint32_t sb, const __half* __restrict__ A,
                                              const __half* __restrict__ BT,
                                              int tid, int row0, int col0, int k0, int K) {
#pragma unroll
    for (int i = 0; i < 4; i++) {
        int ff = tid + i * 256;
        int r  = ff >> 3, c = ff & 7;
        cp16(sb + r * GH_ROW_B + c * 16, &A[(size_t)(row0 + r) * K + k0 + c * 8]);
        cp16(sb + GH_A_BYTES + r * GH_ROW_B + c * 16,
             &BT[(size_t)(col0 + r) * K + k0 + c * 8]);
    }
}

template <bool HALF_OUT>
__global__ __launch_bounds__(256, 2) void gemm_h(const __half* __restrict__ A,
                                                 const __half* __restrict__ BT,
                                                 void* __restrict__ Cv,
                                                 int M, int N, int K) {
    extern __shared__ __align__(16) char gsm[];
    const uint32_t sb = smem_u32(gsm);
    const int tid  = threadIdx.x;
    const int lane = tid & 31;
    const int wid  = tid >> 5;
    const int wr = wid >> 2, wc = wid & 3;
    const int g  = lane >> 2, tig = lane & 3;
    const int row0 = blockIdx.y * 128;
    const int col0 = blockIdx.x * 128;

    float d[4][4][4] = {};
    const int T = K >> 6;

    issue_stage_h(sb + 0 * GH_STAGE, A, BT, tid, row0, col0, 0, K);
    asm volatile("cp.async.commit_group;" ::: "memory");
    issue_stage_h(sb + 1 * GH_STAGE, A, BT, tid, row0, col0, 64, K);
    asm volatile("cp.async.commit_group;" ::: "memory");

    const uint32_t a_base = sb + (wr * 64 + ((lane >> 3) & 1) * 8 + (lane & 7)) * GH_ROW_B
                          + ((lane >> 4) & 1) * 16;

    for (int t = 0; t < T; t++) {
        const int s = t % 3;
        asm volatile("cp.async.wait_group 1;" ::: "memory");
        __syncthreads();

        const uint32_t aS = a_base + s * GH_STAGE;
        const uint32_t* sBu = (const uint32_t*)(gsm + s * GH_STAGE + GH_A_BYTES);

#pragma unroll
        for (int ks = 0; ks < 4; ks++) {
            uint32_t af[4][4], bf[4][2];
#pragma unroll
            for (int ma = 0; ma < 4; ma++)
                LDMATRIX_X4(af[ma], aS + ma * 16 * GH_ROW_B + ks * 32);
#pragma unroll
            for (int na = 0; na < 4; na++) {
                const int n = wc * 32 + na * 8 + g;
                bf[na][0] = sBu[n * 36 + ks * 8 + tig];
                bf[na][1] = sBu[n * 36 + ks * 8 + tig + 4];
            }
#pragma unroll
            for (int ma = 0; ma < 4; ma++)
#pragma unroll
                for (int na = 0; na < 4; na++)
                    MMA_F16(d[ma][na], af[ma], bf[na]);
        }

        if (t + 2 < T)
            issue_stage_h(sb + ((t + 2) % 3) * GH_STAGE, A, BT, tid,
                          row0, col0, (t + 2) * 64, K);
        asm volatile("cp.async.commit_group;" ::: "memory");
    }

#pragma unroll
    for (int ma = 0; ma < 4; ma++)
#pragma unroll
        for (int na = 0; na < 4; na++) {
            const int r = row0 + wr * 64 + ma * 16 + g;
            const int c = col0 + wc * 32 + na * 8 + tig * 2;
            if (HALF_OUT) {
                __half* C = (__half*)Cv;
                *(__half2*)&C[(size_t)r * N + c] =
                    __floats2half2_rn(d[ma][na][0], d[ma][na][1]);
                *(__half2*)&C[(size_t)(r + 8) * N + c] =
                    __floats2half2_rn(d[ma][na][2], d[ma][na][3]);
            } else {
                float* C = (float*)Cv;
                *(float2*)&C[(size_t)r * N + c]       = make_float2(d[ma][na][0], d[ma][na][1]);
                *(float2*)&C[(size_t)(r + 8) * N + c] = make_float2(d[ma][na][2], d[ma][na][3]);
            }
        }
}

// ---------------------------------------------------------------------------
// Fused preprocessing: x -> fp16 ; w_qkv, w_out -> fp16 transposed [N][K]
// ---------------------------------------------------------------------------
#define RN_X  (M_TOTAL * D_MODEL / 4)       // 1048576
#define RN_WQ (D_MODEL * QKV_LD / 4)        //  786432
#define RN_WO (D_MODEL * D_MODEL / 4)       //  262144
#define RN_TOTAL (RN_X + RN_WQ + RN_WO)     // 2097152

__global__ void preproc_kernel(const float* __restrict__ x,
                               const float* __restrict__ wq,
                               const float* __restrict__ wo) {
    int i = blockIdx.x * blockDim.x + threadIdx.x;
    if (i >= RN_TOTAL) return;
    if (i < RN_X) {
        float4 v = ((const float4*)x)[i];
        ((__half2*)g_xh)[2 * i]     = __floats2half2_rn(v.x, v.y);
        ((__half2*)g_xh)[2 * i + 1] = __floats2half2_rn(v.z, v.w);
    } else if (i < RN_X + RN_WQ) {
        int j = i - RN_X;                 // transpose w_qkv [1024][3072] -> [3072][1024]
        int n  = j % QKV_LD;
        int k4 = (j / QKV_LD) * 4;
        __half2 h0 = __floats2half2_rn(wq[(size_t)(k4 + 0) * QKV_LD + n],
                                       wq[(size_t)(k4 + 1) * QKV_LD + n]);
        __half2 h1 = __floats2half2_rn(wq[(size_t)(k4 + 2) * QKV_LD + n],
                                       wq[(size_t)(k4 + 3) * QKV_LD + n]);
        __half2* dst = (__half2*)&g_wqkvT[(size_t)n * D_MODEL + k4];
        dst[0] = h0; dst[1] = h1;
    } else {
        int j = i - RN_X - RN_WQ;         // transpose w_out [1024][1024]
        int n  = j % D_MODEL;
        int k4 = (j / D_MODEL) * 4;
        __half2 h0 = __floats2half2_rn(wo[(size_t)(k4 + 0) * D_MODEL + n],
                                       wo[(size_t)(k4 + 1) * D_MODEL + n]);
        __half2 h1 = __floats2half2_rn(wo[(size_t)(k4 + 2) * D_MODEL + n],
                                       wo[(size_t)(k4 + 3) * D_MODEL + n]);
        __half2* dst = (__half2*)&g_woutT[(size_t)n * D_MODEL + k4];
        dst[0] = h0; dst[1] = h1;
    }
}

// ---------------------------------------------------------------------------
// Causal flash attention — fp16 mma, R16: 64-key tiles (softmax chain runs
// per 64 keys instead of 32 -> per-key softmax overhead halves).
// 64-q tiles, 128 threads (warp = 16 q rows), 3 CTAs/SM, single barrier/iter,
// double-buffered KV cp.async, Q fragments hoisted & pre-scaled by 1/8.
// nkt = qt+1, diag tile only at kt == qt.
// Layouts (fp16): Q/K/V rows 144 B (72 halves: 64 data + pad) — K B-frags are
// contiguous half-pairs (banks 4g+tig+8ks distinct), V via ldmatrix.trans
// (phases (9r+c)%8), P rows 144 B (phases 9r+c, store banks 4g+4na+tig).
// ---------------------------------------------------------------------------
#define FH_ROW    144
#define FH_K_BYTES (64 * FH_ROW)                     // 9216
#define FH_STAGE  (2 * FH_K_BYTES)                   // 18432 (K + V)
#define FH_PS     (2 * FH_STAGE)                     // 36864
#define FH_P_ROW  144
#define FH_SMEM_BYTES (FH_PS + 64 * FH_P_ROW)        // 46080 B

__global__ __launch_bounds__(128, 3) void flash_h_kernel() {
    extern __shared__ __align__(16) char fsmc[];
    const uint32_t sb = smem_u32(fsmc);
    const int tid  = threadIdx.x;
    const int lane = tid & 31;
    const int wid  = tid >> 5;        // warp owns q rows [16wid, 16wid+16)
    const int g    = lane >> 2;
    const int tig  = lane & 3;

    const int qt = (gridDim.x - 1) - blockIdx.x;     // reversed: heavy first
    const int bh = blockIdx.y;
    const int b  = bh >> 4;
    const int h  = bh & 15;
    const int q0 = qt * 64;

    const __half* base = g_qkvh + (size_t)b * T_SEQ * QKV_LD + h * HEAD_DIM;
    const __half* Qg = base;
    const __half* Kg = base + D_MODEL;
    const __half* Vg = base + 2 * D_MODEL;

    // ---- prologue: Q (64x64 halves) -> stage-0 K region; KV(0) -> stage 1 ----
#pragma unroll
    for (int i = 0; i < 4; i++) {
        int ff = tid + i * 128;       // 512 chunks
        int r  = ff >> 3, c = ff & 7;
        cp16(sb + r * FH_ROW + c * 16, &Qg[(size_t)(q0 + r) * QKV_LD + c * 8]);
    }
    asm volatile("cp.async.commit_group;" ::: "memory");
#pragma unroll
    for (int i = 0; i < 4; i++) {
        int ff = tid + i * 128;       // K rows 0..63
        int r  = ff >> 3, c = ff & 7;
        cp16(sb + FH_STAGE + r * FH_ROW + c * 16, &Kg[(size_t)r * QKV_LD + c * 8]);
    }
#pragma unroll
    for (int i = 0; i < 4; i++) {
        int ff = tid + i * 128;
        int r  = ff >> 3, c = ff & 7;
        cp16(sb + FH_STAGE + FH_K_BYTES + r * FH_ROW + c * 16,
             &Vg[(size_t)r * QKV_LD + c * 8]);
    }
    asm volatile("cp.async.commit_group;" ::: "memory");
    asm volatile("cp.async.wait_group 1;" ::: "memory");   // Q complete
    __syncthreads();

    // ---- Q fragments (4 ks of k=16), pre-scaled by 1/8 (exact in fp16) ----
    const int a_row = wid * 16 + ((lane >> 3) & 1) * 8 + (lane & 7);
    const int a_seg = (lane >> 4) & 1;
    uint32_t qf[4][4];
    {
        const __half2 sc = __float2half2_rn(0.125f);
        const uint32_t q_lm = sb + a_row * FH_ROW + a_seg * 16;
#pragma unroll
        for (int ks = 0; ks < 4; ks++) {
            LDMATRIX_X4(qf[ks], q_lm + ks * 32);
#pragma unroll
            for (int r = 0; r < 4; r++) {
                __half2 hv = *reinterpret_cast<__half2*>(&qf[ks][r]);
                hv = __hmul2(hv, sc);
                qf[ks][r] = *reinterpret_cast<uint32_t*>(&hv);
            }
        }
    }
    // no barrier: iter-0's top barrier orders extraction vs stage-0 overwrite

    const uint32_t p_lm = sb + FH_PS + a_row * FH_P_ROW + a_seg * 16;
    const uint32_t v_off = ((lane & 7) + ((lane >> 3) & 1) * 8) * FH_ROW
                         + ((lane >> 4) & 1) * 16;

    const float NEG_INF = __int_as_float(0xff800000u);
    float o[8][4] = {};
    float m0 = NEG_INF, m1 = NEG_INF, l0 = 0.f, l1 = 0.f;

    const int nkt = qt + 1;                           // 64-key tiles
    for (int kt = 0; kt < nkt; kt++) {
        const int s = (kt + 1) & 1;                   // stage holding KV(kt)

        asm volatile("cp.async.wait_group 0;" ::: "memory");
        __syncthreads();          // (a) KV(kt) visible; (b) stage (kt&1) free

        // prefetch KV(kt+1) into the stage just freed
        if (kt + 1 < nkt) {
            const int sd = kt & 1;
            const size_t krow0 = (size_t)(kt + 1) * 64;
#pragma unroll
            for (int i = 0; i < 4; i++) {
                int ff = tid + i * 128;
                int r  = ff >> 3, c = ff & 7;
                cp16(sb + sd * FH_STAGE + r * FH_ROW + c * 16,
                     &Kg[(krow0 + r) * QKV_LD + c * 8]);
            }
#pragma unroll
            for (int i = 0; i < 4; i++) {
                int ff = tid + i * 128;
                int r  = ff >> 3, c = ff & 7;
                cp16(sb + sd * FH_STAGE + FH_K_BYTES + r * FH_ROW + c * 16,
                     &Vg[(krow0 + r) * QKV_LD + c * 8]);
            }
            asm volatile("cp.async.commit_group;" ::: "memory");
        }

        const uint32_t* Ku = (const uint32_t*)(fsmc + s * FH_STAGE);
        const uint32_t vS  = sb + s * FH_STAGE + FH_K_BYTES;

        // ---- S = Q K^T : 4 ks (k=16) x 8 na (64 keys) ----
        float sfrag[8][4] = {};
#pragma unroll
        for (int ks = 0; ks < 4; ks++) {
#pragma unroll
            for (int na = 0; na < 8; na++) {
                uint32_t bf[2];
                bf[0] = Ku[(na * 8 + g) * 36 + ks * 8 + tig];
                bf[1] = Ku[(na * 8 + g) * 36 + ks * 8 + tig + 4];
                MMA_F16(sfrag[na], qf[ks], bf);
            }
        }

        // ---- causal mask (scores pre-scaled via Q) ----
        if (kt == qt) {
            const int qr0 = q0 + wid * 16 + g;
            const int qr1 = qr0 + 8;
#pragma unroll
            for (int na = 0; na < 8; na++) {
                const int kg = kt * 64 + na * 8 + 2 * tig;
                if (kg     > qr0) sfrag[na][0] = NEG_INF;
                if (kg + 1 > qr0) sfrag[na][1] = NEG_INF;
                if (kg     > qr1) sfrag[na][2] = NEG_INF;
                if (kg + 1 > qr1) sfrag[na][3] = NEG_INF;
            }
        }

        // ---- online softmax (rows g / g+8; reduce across quad tig) ----
        float mx0 = NEG_INF, mx1 = NEG_INF;
#pragma unroll
        for (int na = 0; na < 8; na++) {
            mx0 = fmaxf(mx0, fmaxf(sfrag[na][0], sfrag[na][1]));
            mx1 = fmaxf(mx1, fmaxf(sfrag[na][2], sfrag[na][3]));
        }
        mx0 = fmaxf(mx0, __shfl_xor_sync(0xffffffffu, mx0, 1));
        mx0 = fmaxf(mx0, __shfl_xor_sync(0xffffffffu, mx0, 2));
        mx1 = fmaxf(mx1, __shfl_xor_sync(0xffffffffu, mx1, 1));
        mx1 = fmaxf(mx1, __shfl_xor_sync(0xffffffffu, mx1, 2));
        const float mn0 = fmaxf(m0, mx0);
        const float mn1 = fmaxf(m1, mx1);
        const float a0 = __expf(m0 - mn0);
        const float a1 = __expf(m1 - mn1);
        float sum0 = 0.f, sum1 = 0.f;
#pragma unroll
        for (int na = 0; na < 8; na++) {
            sfrag[na][0] = __expf(sfrag[na][0] - mn0);
            sfrag[na][1] = __expf(sfrag[na][1] - mn0);
            sfrag[na][2] = __expf(sfrag[na][2] - mn1);
            sfrag[na][3] = __expf(sfrag[na][3] - mn1);
            sum0 += sfrag[na][0] + sfrag[na][1];
            sum1 += sfrag[na][2] + sfrag[na][3];
        }
        sum0 += __shfl_xor_sync(0xffffffffu, sum0, 1);
        sum0 += __shfl_xor_sync(0xffffffffu, sum0, 2);
        sum1 += __shfl_xor_sync(0xffffffffu, sum1, 1);
        sum1 += __shfl_xor_sync(0xffffffffu, sum1, 2);
        l0 = l0 * a0 + sum0;  m0 = mn0;
        l1 = l1 * a1 + sum1;  m1 = mn1;
#pragma unroll
        for (int na = 0; na < 8; na++) {
            o[na][0] *= a0; o[na][1] *= a0;
            o[na][2] *= a1; o[na][3] *= a1;
        }

        // ---- P (fp16) -> warp-private smem rows; __syncwarp suffices ----
        {
            const int pr0 = wid * 16 + g;
#pragma unroll
            for (int na = 0; na < 8; na++) {
                *(__half2*)(fsmc + FH_PS + pr0 * FH_P_ROW + (na * 8 + 2 * tig) * 2) =
                    __floats2half2_rn(sfrag[na][0], sfrag[na][1]);
                *(__half2*)(fsmc + FH_PS + (pr0 + 8) * FH_P_ROW + (na * 8 + 2 * tig) * 2) =
                    __floats2half2_rn(sfrag[na][2], sfrag[na][3]);
            }
        }
        __syncwarp();

        // ---- O += P V : 4 ks (k=16 keys) x 8 na (64 d) via ldmatrix.trans ----
#pragma unroll
        for (int ks = 0; ks < 4; ks++) {
            uint32_t pf[4];
            LDMATRIX_X4(pf, p_lm + ks * 32);
#pragma unroll
            for (int np = 0; np < 4; np++) {
                uint32_t vf[4];
                LDMATRIX_X4_T(vf, vS + v_off + ks * 16 * FH_ROW + np * 32);
                MMA_F16(o[np * 2],     pf, vf);
                MMA_F16(o[np * 2 + 1], pf, vf + 2);
            }
        }
        // no bottom barrier: next iter's top barrier provides the ordering
    }

    // ---- epilogue: /l, fp16 (A operand of fp16 out-proj), store ----
    const float i0 = 1.f / l0;
    const float i1 = 1.f / l1;
    const int r0 = q0 + wid * 16 + g;
    __half* out0 = &g_attnh[(size_t)(b * T_SEQ + r0) * D_MODEL + h * HEAD_DIM + 2 * tig];
    __half* out1 = &g_attnh[(size_t)(b * T_SEQ + r0 + 8) * D_MODEL + h * HEAD_DIM + 2 * tig];
#pragma unroll
    for (int na = 0; na < 8; na++) {
        *(__half2*)&out0[na * 8] = __floats2half2_rn(o[na][0] * i0, o[na][1] * i0);
        *(__half2*)&out1[na * 8] = __floats2half2_rn(o[na][2] * i1, o[na][3] * i1);
    }
}

// ---------------------------------------------------------------------------
// Launch
// ---------------------------------------------------------------------------
extern "C" void kernel_launch(void* const* d_in, const int* in_sizes, int n_in,
                              void* d_out, int out_size) {
    const float* x     = (const float*)d_in[0];   // [2,2048,1024]
    const float* w_qkv = (const float*)d_in[1];   // [1024,3072]
    const float* w_out = (const float*)d_in[2];   // [1024,1024]
    float* out = (float*)d_out;                   // [2,2048,1024]

    void *qkvh_p, *attnh_p, *xh_p, *wqkvT_p, *woutT_p;
    cudaGetSymbolAddress(&qkvh_p,  g_qkvh);
    cudaGetSymbolAddress(&attnh_p, g_attnh);
    cudaGetSymbolAddress(&xh_p,    g_xh);
    cudaGetSymbolAddress(&wqkvT_p, g_wqkvT);
    cudaGetSymbolAddress(&woutT_p, g_woutT);

    cudaFuncSetAttribute(flash_h_kernel,
                         cudaFuncAttributeMaxDynamicSharedMemorySize, FH_SMEM_BYTES);
    cudaFuncSetAttribute(gemm_h<true>,
                         cudaFuncAttributeMaxDynamicSharedMemorySize, GH_SMEM_BYTES);
    cudaFuncSetAttribute(gemm_h<false>,
                         cudaFuncAttributeMaxDynamicSharedMemorySize, GH_SMEM_BYTES);

    // 0) fused preprocess: x -> fp16; weights -> fp16 transposed
    preproc_kernel<<<(RN_TOTAL + 255) / 256, 256>>>(x, w_qkv, w_out);

    // 1) QKV projection (fp16 mma, fp16 output for flash)
    gemm_h<true><<<dim3(QKV_LD / 128, M_TOTAL / 128), 256, GH_SMEM_BYTES>>>(
        (const __half*)xh_p, (const __half*)wqkvT_p, qkvh_p,
        M_TOTAL, QKV_LD, D_MODEL);

    // 2) causal flash attention (fp16 mma, 64-key tiles, 3 CTAs/SM)
    flash_h_kernel<<<dim3(T_SEQ / 64, BATCH * N_HEADS), 128, FH_SMEM_BYTES>>>();

    // 3) output projection (fp16 mma, fp32 output)
    gemm_h<false><<<dim3(D_MODEL / 128, M_TOTAL / 128), 256, GH_SMEM_BYTES>>>(
        (const __half*)attnh_p, (const __half*)woutT_p, out,
        M_TOTAL, D_MODEL, D_MODEL);
}

// round 17
// speedup vs baseline: 1.8323x; 1.0135x over previous
#include <cuda_runtime.h>
#include <cuda_fp16.h>
#include <math.h>
#include <stdint.h>

// Problem constants
#define BATCH    2
#define T_SEQ    2048
#define D_MODEL  1024
#define N_HEADS  16
#define HEAD_DIM 64
#define M_TOTAL  (BATCH * T_SEQ)          // 4096 rows
#define QKV_LD   (3 * D_MODEL)            // 3072

// Scratch (allocation-free rule: __device__ globals)
__device__ __half g_qkvh  [M_TOTAL * QKV_LD];    // [4096, 3072] fp16 QKV
__device__ __half g_attnh [M_TOTAL * D_MODEL];   // [4096, 1024] fp16 attention out
__device__ __half g_xh    [M_TOTAL * D_MODEL];   // fp16 x
__device__ __half g_wqkvT [QKV_LD * D_MODEL];    // fp16 w_qkv^T  [3072][1024]
__device__ __half g_woutT [D_MODEL * D_MODEL];   // fp16 w_out^T  [1024][1024]

__device__ __forceinline__ uint32_t smem_u32(const void* p) {
    uint32_t a;
    asm("{ .reg .u64 t; cvta.to.shared.u64 t, %1; cvt.u32.u64 %0, t; }" : "=r"(a) : "l"(p));
    return a;
}
__device__ __forceinline__ void cp16(uint32_t dst, const void* src) {
    asm volatile("cp.async.cg.shared.global [%0], [%1], 16;" :: "r"(dst), "l"(src) : "memory");
}
#define MMA_F16(D, A, B) \
    asm volatile("mma.sync.aligned.m16n8k16.row.col.f32.f16.f16.f32 " \
                 "{%0,%1,%2,%3}, {%4,%5,%6,%7}, {%8,%9}, {%0,%1,%2,%3};" \
                 : "+f"((D)[0]), "+f"((D)[1]), "+f"((D)[2]), "+f"((D)[3]) \
                 : "r"((A)[0]), "r"((A)[1]), "r"((A)[2]), "r"((A)[3]), \
                   "r"((B)[0]), "r"((B)[1]))
#define LDMATRIX_X4(R, ADDR) \
    asm volatile("ldmatrix.sync.aligned.m8n8.x4.shared.b16 {%0,%1,%2,%3}, [%4];" \
                 : "=r"((R)[0]), "=r"((R)[1]), "=r"((R)[2]), "=r"((R)[3]) : "r"(ADDR))
#define LDMATRIX_X4_T(R, ADDR) \
    asm volatile("ldmatrix.sync.aligned.m8n8.x4.trans.shared.b16 {%0,%1,%2,%3}, [%4];" \
                 : "=r"((R)[0]), "=r"((R)[1]), "=r"((R)[2]), "=r"((R)[3]) : "r"(ADDR))

// ---------------------------------------------------------------------------
// fp16 mma.sync GEMM (validated): C[M,N] = A[M,K] @ B_T[N,K]^T, fp32 acc.
// 128x128 block, 8 warps (2x4), warp 64x32, K-tile 64, 3-stage cp.async.
// ---------------------------------------------------------------------------
#define GH_ROW_B   144
#define GH_A_BYTES (128 * GH_ROW_B)
#define GH_STAGE   (2 * GH_A_BYTES)               // 36864 B
#define GH_SMEM_BYTES (3 * GH_STAGE)              // 110592 B

__device__ __forceinline__ void issue_stage_h(uint32_t sb, const __half* __restrict__ A,
                                              const __half* __restrict__ BT,
                                              int tid, int row0, int col0, int k0, int K) {
#pragma unroll
    for (int i = 0; i < 4; i++) {
        int ff = tid + i * 256;
        int r  = ff >> 3, c = ff & 7;
        cp16(sb + r * GH_ROW_B + c * 16, &A[(size_t)(row0 + r) * K + k0 + c * 8]);
        cp16(sb + GH_A_BYTES + r * GH_ROW_B + c * 16,
             &BT[(size_t)(col0 + r) * K + k0 + c * 8]);
    }
}

template <bool HALF_OUT>
__global__ __launch_bounds__(256, 2) void gemm_h(const __half* __restrict__ A,
                                                 const __half* __restrict__ BT,
                                                 void* __restrict__ Cv,
                                                 int M, int N, int K) {
    extern __shared__ __align__(16) char gsm[];
    const uint32_t sb = smem_u32(gsm);
    const int tid  = threadIdx.x;
    const int lane = tid & 31;
    const int wid  = tid >> 5;
    const int wr = wid >> 2, wc = wid & 3;
    const int g  = lane >> 2, tig = lane & 3;
    const int row0 = blockIdx.y * 128;
    const int col0 = blockIdx.x * 128;

    float d[4][4][4] = {};
    const int T = K >> 6;

    issue_stage_h(sb + 0 * GH_STAGE, A, BT, tid, row0, col0, 0, K);
    asm volatile("cp.async.commit_group;" ::: "memory");
    issue_stage_h(sb + 1 * GH_STAGE, A, BT, tid, row0, col0, 64, K);
    asm volatile("cp.async.commit_group;" ::: "memory");

    const uint32_t a_base = sb + (wr * 64 + ((lane >> 3) & 1) * 8 + (lane & 7)) * GH_ROW_B
                          + ((lane >> 4) & 1) * 16;

    for (int t = 0; t < T; t++) {
        const int s = t % 3;
        asm volatile("cp.async.wait_group 1;" ::: "memory");
        __syncthreads();

        const uint32_t aS = a_base + s * GH_STAGE;
        const uint32_t* sBu = (const uint32_t*)(gsm + s * GH_STAGE + GH_A_BYTES);

#pragma unroll
        for (int ks = 0; ks < 4; ks++) {
            uint32_t af[4][4], bf[4][2];
#pragma unroll
            for (int ma = 0; ma < 4; ma++)
                LDMATRIX_X4(af[ma], aS + ma * 16 * GH_ROW_B + ks * 32);
#pragma unroll
            for (int na = 0; na < 4; na++) {
                const int n = wc * 32 + na * 8 + g;
                bf[na][0] = sBu[n * 36 + ks * 8 + tig];
                bf[na][1] = sBu[n * 36 + ks * 8 + tig + 4];
            }
#pragma unroll
            for (int ma = 0; ma < 4; ma++)
#pragma unroll
                for (int na = 0; na < 4; na++)
                    MMA_F16(d[ma][na], af[ma], bf[na]);
        }

        if (t + 2 < T)
            issue_stage_h(sb + ((t + 2) % 3) * GH_STAGE, A, BT, tid,
                          row0, col0, (t + 2) * 64, K);
        asm volatile("cp.async.commit_group;" ::: "memory");
    }

#pragma unroll
    for (int ma = 0; ma < 4; ma++)
#pragma unroll
        for (int na = 0; na < 4; na++) {
            const int r = row0 + wr * 64 + ma * 16 + g;
            const int c = col0 + wc * 32 + na * 8 + tig * 2;
            if (HALF_OUT) {
                __half* C = (__half*)Cv;
                *(__half2*)&C[(size_t)r * N + c] =
                    __floats2half2_rn(d[ma][na][0], d[ma][na][1]);
                *(__half2*)&C[(size_t)(r + 8) * N + c] =
                    __floats2half2_rn(d[ma][na][2], d[ma][na][3]);
            } else {
                float* C = (float*)Cv;
                *(float2*)&C[(size_t)r * N + c]       = make_float2(d[ma][na][0], d[ma][na][1]);
                *(float2*)&C[(size_t)(r + 8) * N + c] = make_float2(d[ma][na][2], d[ma][na][3]);
            }
        }
}

// ---------------------------------------------------------------------------
// Fused preprocessing: x -> fp16 ; w_qkv, w_out -> fp16 transposed [N][K]
// ---------------------------------------------------------------------------
#define RN_X  (M_TOTAL * D_MODEL / 4)       // 1048576
#define RN_WQ (D_MODEL * QKV_LD / 4)        //  786432
#define RN_WO (D_MODEL * D_MODEL / 4)       //  262144
#define RN_TOTAL (RN_X + RN_WQ + RN_WO)     // 2097152

__global__ void preproc_kernel(const float* __restrict__ x,
                               const float* __restrict__ wq,
                               const float* __restrict__ wo) {
    int i = blockIdx.x * blockDim.x + threadIdx.x;
    if (i >= RN_TOTAL) return;
    if (i < RN_X) {
        float4 v = ((const float4*)x)[i];
        ((__half2*)g_xh)[2 * i]     = __floats2half2_rn(v.x, v.y);
        ((__half2*)g_xh)[2 * i + 1] = __floats2half2_rn(v.z, v.w);
    } else if (i < RN_X + RN_WQ) {
        int j = i - RN_X;
        int n  = j % QKV_LD;
        int k4 = (j / QKV_LD) * 4;
        __half2 h0 = __floats2half2_rn(wq[(size_t)(k4 + 0) * QKV_LD + n],
                                       wq[(size_t)(k4 + 1) * QKV_LD + n]);
        __half2 h1 = __floats2half2_rn(wq[(size_t)(k4 + 2) * QKV_LD + n],
                                       wq[(size_t)(k4 + 3) * QKV_LD + n]);
        __half2* dst = (__half2*)&g_wqkvT[(size_t)n * D_MODEL + k4];
        dst[0] = h0; dst[1] = h1;
    } else {
        int j = i - RN_X - RN_WQ;
        int n  = j % D_MODEL;
        int k4 = (j / D_MODEL) * 4;
        __half2 h0 = __floats2half2_rn(wo[(size_t)(k4 + 0) * D_MODEL + n],
                                       wo[(size_t)(k4 + 1) * D_MODEL + n]);
        __half2 h1 = __floats2half2_rn(wo[(size_t)(k4 + 2) * D_MODEL + n],
                                       wo[(size_t)(k4 + 3) * D_MODEL + n]);
        __half2* dst = (__half2*)&g_woutT[(size_t)n * D_MODEL + k4];
        dst[0] = h0; dst[1] = h1;
    }
}

// ---------------------------------------------------------------------------
// Causal flash attention — fp16 mma, R17:
//  * 4 CTAs/SM restored (46 KB x 4 = 184 KB fits; regs ~100)
//  * l kept as thread-partial sums (quad-uniform rescale factor), quad-reduced
//    ONCE in the epilogue -> 4 shfls removed from the per-iter serial chain
// 64-q tiles, 64-key tiles, single barrier/iter, double-buffered KV cp.async,
// Q fragments hoisted & pre-scaled by 1/8. nkt = qt+1, diag at kt == qt.
// ---------------------------------------------------------------------------
#define FH_ROW    144
#define FH_K_BYTES (64 * FH_ROW)                     // 9216
#define FH_STAGE  (2 * FH_K_BYTES)                   // 18432 (K + V)
#define FH_PS     (2 * FH_STAGE)                     // 36864
#define FH_P_ROW  144
#define FH_SMEM_BYTES (FH_PS + 64 * FH_P_ROW)        // 46080 B

__global__ __launch_bounds__(128, 4) void flash_h_kernel() {
    extern __shared__ __align__(16) char fsmc[];
    const uint32_t sb = smem_u32(fsmc);
    const int tid  = threadIdx.x;
    const int lane = tid & 31;
    const int wid  = tid >> 5;        // warp owns q rows [16wid, 16wid+16)
    const int g    = lane >> 2;
    const int tig  = lane & 3;

    const int qt = (gridDim.x - 1) - blockIdx.x;     // reversed: heavy first
    const int bh = blockIdx.y;
    const int b  = bh >> 4;
    const int h  = bh & 15;
    const int q0 = qt * 64;

    const __half* base = g_qkvh + (size_t)b * T_SEQ * QKV_LD + h * HEAD_DIM;
    const __half* Qg = base;
    const __half* Kg = base + D_MODEL;
    const __half* Vg = base + 2 * D_MODEL;

    // ---- prologue: Q (64x64 halves) -> stage-0 K region; KV(0) -> stage 1 ----
#pragma unroll
    for (int i = 0; i < 4; i++) {
        int ff = tid + i * 128;
        int r  = ff >> 3, c = ff & 7;
        cp16(sb + r * FH_ROW + c * 16, &Qg[(size_t)(q0 + r) * QKV_LD + c * 8]);
    }
    asm volatile("cp.async.commit_group;" ::: "memory");
#pragma unroll
    for (int i = 0; i < 4; i++) {
        int ff = tid + i * 128;
        int r  = ff >> 3, c = ff & 7;
        cp16(sb + FH_STAGE + r * FH_ROW + c * 16, &Kg[(size_t)r * QKV_LD + c * 8]);
    }
#pragma unroll
    for (int i = 0; i < 4; i++) {
        int ff = tid + i * 128;
        int r  = ff >> 3, c = ff & 7;
        cp16(sb + FH_STAGE + FH_K_BYTES + r * FH_ROW + c * 16,
             &Vg[(size_t)r * QKV_LD + c * 8]);
    }
    asm volatile("cp.async.commit_group;" ::: "memory");
    asm volatile("cp.async.wait_group 1;" ::: "memory");   // Q complete
    __syncthreads();

    // ---- Q fragments (4 ks of k=16), pre-scaled by 1/8 (exact in fp16) ----
    const int a_row = wid * 16 + ((lane >> 3) & 1) * 8 + (lane & 7);
    const int a_seg = (lane >> 4) & 1;
    uint32_t qf[4][4];
    {
        const __half2 sc = __float2half2_rn(0.125f);
        const uint32_t q_lm = sb + a_row * FH_ROW + a_seg * 16;
#pragma unroll
        for (int ks = 0; ks < 4; ks++) {
            LDMATRIX_X4(qf[ks], q_lm + ks * 32);
#pragma unroll
            for (int r = 0; r < 4; r++) {
                __half2 hv = *reinterpret_cast<__half2*>(&qf[ks][r]);
                hv = __hmul2(hv, sc);
                qf[ks][r] = *reinterpret_cast<uint32_t*>(&hv);
            }
        }
    }
    // no barrier: iter-0's top barrier orders extraction vs stage-0 overwrite

    const uint32_t p_lm = sb + FH_PS + a_row * FH_P_ROW + a_seg * 16;
    const uint32_t v_off = ((lane & 7) + ((lane >> 3) & 1) * 8) * FH_ROW
                         + ((lane >> 4) & 1) * 16;

    const float NEG_INF = __int_as_float(0xff800000u);
    float o[8][4] = {};
    float m0 = NEG_INF, m1 = NEG_INF;
    float l0 = 0.f, l1 = 0.f;          // THREAD-PARTIAL sums (reduced at end)

    const int nkt = qt + 1;                           // 64-key tiles
    for (int kt = 0; kt < nkt; kt++) {
        const int s = (kt + 1) & 1;                   // stage holding KV(kt)

        asm volatile("cp.async.wait_group 0;" ::: "memory");
        __syncthreads();          // (a) KV(kt) visible; (b) stage (kt&1) free

        // prefetch KV(kt+1) into the stage just freed
        if (kt + 1 < nkt) {
            const int sd = kt & 1;
            const size_t krow0 = (size_t)(kt + 1) * 64;
#pragma unroll
            for (int i = 0; i < 4; i++) {
                int ff = tid + i * 128;
                int r  = ff >> 3, c = ff & 7;
                cp16(sb + sd * FH_STAGE + r * FH_ROW + c * 16,
                     &Kg[(krow0 + r) * QKV_LD + c * 8]);
            }
#pragma unroll
            for (int i = 0; i < 4; i++) {
                int ff = tid + i * 128;
                int r  = ff >> 3, c = ff & 7;
                cp16(sb + sd * FH_STAGE + FH_K_BYTES + r * FH_ROW + c * 16,
                     &Vg[(krow0 + r) * QKV_LD + c * 8]);
            }
            asm volatile("cp.async.commit_group;" ::: "memory");
        }

        const uint32_t* Ku = (const uint32_t*)(fsmc + s * FH_STAGE);
        const uint32_t vS  = sb + s * FH_STAGE + FH_K_BYTES;

        // ---- S = Q K^T : 4 ks (k=16) x 8 na (64 keys) ----
        float sfrag[8][4] = {};
#pragma unroll
        for (int ks = 0; ks < 4; ks++) {
#pragma unroll
            for (int na = 0; na < 8; na++) {
                uint32_t bf[2];
                bf[0] = Ku[(na * 8 + g) * 36 + ks * 8 + tig];
                bf[1] = Ku[(na * 8 + g) * 36 + ks * 8 + tig + 4];
                MMA_F16(sfrag[na], qf[ks], bf);
            }
        }

        // ---- causal mask (scores pre-scaled via Q) ----
        if (kt == qt) {
            const int qr0 = q0 + wid * 16 + g;
            const int qr1 = qr0 + 8;
#pragma unroll
            for (int na = 0; na < 8; na++) {
                const int kg = kt * 64 + na * 8 + 2 * tig;
                if (kg     > qr0) sfrag[na][0] = NEG_INF;
                if (kg + 1 > qr0) sfrag[na][1] = NEG_INF;
                if (kg     > qr1) sfrag[na][2] = NEG_INF;
                if (kg + 1 > qr1) sfrag[na][3] = NEG_INF;
            }
        }

        // ---- online softmax: max quad-reduced; l stays thread-partial ----
        float mx0 = NEG_INF, mx1 = NEG_INF;
#pragma unroll
        for (int na = 0; na < 8; na++) {
            mx0 = fmaxf(mx0, fmaxf(sfrag[na][0], sfrag[na][1]));
            mx1 = fmaxf(mx1, fmaxf(sfrag[na][2], sfrag[na][3]));
        }
        mx0 = fmaxf(mx0, __shfl_xor_sync(0xffffffffu, mx0, 1));
        mx0 = fmaxf(mx0, __shfl_xor_sync(0xffffffffu, mx0, 2));
        mx1 = fmaxf(mx1, __shfl_xor_sync(0xffffffffu, mx1, 1));
        mx1 = fmaxf(mx1, __shfl_xor_sync(0xffffffffu, mx1, 2));
        const float mn0 = fmaxf(m0, mx0);
        const float mn1 = fmaxf(m1, mx1);
        const float a0 = __expf(m0 - mn0);   // quad-uniform
        const float a1 = __expf(m1 - mn1);
        float sum0 = 0.f, sum1 = 0.f;
#pragma unroll
        for (int na = 0; na < 8; na++) {
            sfrag[na][0] = __expf(sfrag[na][0] - mn0);
            sfrag[na][1] = __expf(sfrag[na][1] - mn0);
            sfrag[na][2] = __expf(sfrag[na][2] - mn1);
            sfrag[na][3] = __expf(sfrag[na][3] - mn1);
            sum0 += sfrag[na][0] + sfrag[na][1];
            sum1 += sfrag[na][2] + sfrag[na][3];
        }
        l0 = l0 * a0 + sum0;  m0 = mn0;      // no shfl: partial per thread
        l1 = l1 * a1 + sum1;  m1 = mn1;
#pragma unroll
        for (int na = 0; na < 8; na++) {
            o[na][0] *= a0; o[na][1] *= a0;
            o[na][2] *= a1; o[na][3] *= a1;
        }

        // ---- P (fp16) -> warp-private smem rows; __syncwarp suffices ----
        {
            const int pr0 = wid * 16 + g;
#pragma unroll
            for (int na = 0; na < 8; na++) {
                *(__half2*)(fsmc + FH_PS + pr0 * FH_P_ROW + (na * 8 + 2 * tig) * 2) =
                    __floats2half2_rn(sfrag[na][0], sfrag[na][1]);
                *(__half2*)(fsmc + FH_PS + (pr0 + 8) * FH_P_ROW + (na * 8 + 2 * tig) * 2) =
                    __floats2half2_rn(sfrag[na][2], sfrag[na][3]);
            }
        }
        __syncwarp();

        // ---- O += P V : 4 ks (k=16 keys) x 8 na (64 d) via ldmatrix.trans ----
#pragma unroll
        for (int ks = 0; ks < 4; ks++) {
            uint32_t pf[4];
            LDMATRIX_X4(pf, p_lm + ks * 32);
#pragma unroll
            for (int np = 0; np < 4; np++) {
                uint32_t vf[4];
                LDMATRIX_X4_T(vf, vS + v_off + ks * 16 * FH_ROW + np * 32);
                MMA_F16(o[np * 2],     pf, vf);
                MMA_F16(o[np * 2 + 1], pf, vf + 2);
            }
        }
        // no bottom barrier: next iter's top barrier provides the ordering
    }

    // ---- epilogue: quad-reduce l once, /l, fp16 store ----
    l0 += __shfl_xor_sync(0xffffffffu, l0, 1);
    l0 += __shfl_xor_sync(0xffffffffu, l0, 2);
    l1 += __shfl_xor_sync(0xffffffffu, l1, 1);
    l1 += __shfl_xor_sync(0xffffffffu, l1, 2);
    const float i0 = 1.f / l0;
    const float i1 = 1.f / l1;
    const int r0 = q0 + wid * 16 + g;
    __half* out0 = &g_attnh[(size_t)(b * T_SEQ + r0) * D_MODEL + h * HEAD_DIM + 2 * tig];
    __half* out1 = &g_attnh[(size_t)(b * T_SEQ + r0 + 8) * D_MODEL + h * HEAD_DIM + 2 * tig];
#pragma unroll
    for (int na = 0; na < 8; na++) {
        *(__half2*)&out0[na * 8] = __floats2half2_rn(o[na][0] * i0, o[na][1] * i0);
        *(__half2*)&out1[na * 8] = __floats2half2_rn(o[na][2] * i1, o[na][3] * i1);
    }
}

// ---------------------------------------------------------------------------
// Launch
// ---------------------------------------------------------------------------
extern "C" void kernel_launch(void* const* d_in, const int* in_sizes, int n_in,
                              void* d_out, int out_size) {
    const float* x     = (const float*)d_in[0];   // [2,2048,1024]
    const float* w_qkv = (const float*)d_in[1];   // [1024,3072]
    const float* w_out = (const float*)d_in[2];   // [1024,1024]
    float* out = (float*)d_out;                   // [2,2048,1024]

    void *qkvh_p, *attnh_p, *xh_p, *wqkvT_p, *woutT_p;
    cudaGetSymbolAddress(&qkvh_p,  g_qkvh);
    cudaGetSymbolAddress(&attnh_p, g_attnh);
    cudaGetSymbolAddress(&xh_p,    g_xh);
    cudaGetSymbolAddress(&wqkvT_p, g_wqkvT);
    cudaGetSymbolAddress(&woutT_p, g_woutT);

    cudaFuncSetAttribute(flash_h_kernel,
                         cudaFuncAttributeMaxDynamicSharedMemorySize, FH_SMEM_BYTES);
    cudaFuncSetAttribute(gemm_h<true>,
                         cudaFuncAttributeMaxDynamicSharedMemorySize, GH_SMEM_BYTES);
    cudaFuncSetAttribute(gemm_h<false>,
                         cudaFuncAttributeMaxDynamicSharedMemorySize, GH_SMEM_BYTES);

    // 0) fused preprocess: x -> fp16; weights -> fp16 transposed
    preproc_kernel<<<(RN_TOTAL + 255) / 256, 256>>>(x, w_qkv, w_out);

    // 1) QKV projection (fp16 mma, fp16 output for flash)
    gemm_h<true><<<dim3(QKV_LD / 128, M_TOTAL / 128), 256, GH_SMEM_BYTES>>>(
        (const __half*)xh_p, (const __half*)wqkvT_p, qkvh_p,
        M_TOTAL, QKV_LD, D_MODEL);

    // 2) causal flash attention (fp16 mma, 64-key tiles, 4 CTAs/SM)
    flash_h_kernel<<<dim3(T_SEQ / 64, BATCH * N_HEADS), 128, FH_SMEM_BYTES>>>();

    // 3) output projection (fp16 mma, fp32 output)
    gemm_h<false><<<dim3(D_MODEL / 128, M_TOTAL / 128), 256, GH_SMEM_BYTES>>>(
        (const __half*)attnh_p, (const __half*)woutT_p, out,
        M_TOTAL, D_MODEL, D_MODEL);
}